// round 9
// baseline (speedup 1.0000x reference)
#include <cuda_runtime.h>
#include <cstdint>

// Problem constants
#define BB 8
#define TT 2048
#define EE 1024
#define HDD 64
#define MM (BB * TT)          // 16384 rows
// SCALE * log2(e): folded into Q so softmax runs in base-2 domain
#define SCALE_LOG2E 0.1803368801111601f

// Scratch for q,k,v projections (stored pre-rounded to tf32), 4 MB each
__device__ float g_q[MM * HDD];
__device__ float g_k[MM * HDD];
__device__ float g_v[MM * HDD];
// Split-kv partials: [b][qt][chunk] x (128 rows x 64 cols) + per-row m,l
__device__ float g_po[BB * 16 * 4 * 128 * HDD];
__device__ float g_pm[BB * 16 * 4 * 128];
__device__ float g_pl[BB * 16 * 4 * 128];

// ---------------------------------------------------------------------------
// helpers
// ---------------------------------------------------------------------------
__device__ __forceinline__ float f2tff(float x) {
    uint32_t u;
    asm("cvt.rna.tf32.f32 %0, %1;" : "=r"(u) : "f"(x));
    return __uint_as_float(u);
}

__device__ __forceinline__ float ex2(float x) {
    float r;
    asm("ex2.approx.f32 %0, %1;" : "=f"(r) : "f"(x));
    return r;
}

__device__ __forceinline__ void mma8(float* c, const uint32_t* a, const uint32_t* b) {
    asm volatile(
        "mma.sync.aligned.m16n8k8.row.col.f32.tf32.tf32.f32 "
        "{%0,%1,%2,%3}, {%4,%5,%6,%7}, {%8,%9}, {%0,%1,%2,%3};"
        : "+f"(c[0]), "+f"(c[1]), "+f"(c[2]), "+f"(c[3])
        : "r"(a[0]), "r"(a[1]), "r"(a[2]), "r"(a[3]), "r"(b[0]), "r"(b[1]));
}

// ---------------------------------------------------------------------------
// Stage 1: fused QKV projection (exact R2 config — measured 54.7us).
// CTA tile 128 rows x 192 cols (Q|K|V heads). grid 128, block 256.
// Register-double-buffered smem, ONE __syncthreads per 32-wide k-chunk.
// ---------------------------------------------------------------------------
#define XS_STRIDE 36          // 36 % 32 == 4 -> conflict-friendly
#define WS3_STRIDE 196        // 196 % 32 == 4
#define XS_BUF (128 * XS_STRIDE)
#define WS_BUF (32 * WS3_STRIDE)
#define QKV_SMEM_BYTES ((2 * XS_BUF + 2 * WS_BUF) * 4)   // 87040

__global__ __launch_bounds__(256) void qkv_kernel(
    const float* __restrict__ x,
    const float* __restrict__ Wq,
    const float* __restrict__ Wk,
    const float* __restrict__ Wv)
{
    extern __shared__ float sm[];
    float* Xs = sm;                     // [2][128*36]
    float* Ws = sm + 2 * XS_BUF;        // [2][32*196]

    const int tid  = threadIdx.x;
    const int warp = tid >> 5;
    const int lane = tid & 31;
    const int qd   = lane & 3;
    const int gp   = lane >> 2;
    const int wr   = warp & 1;          // row half (0/1) -> 64 rows
    const int wc   = warp >> 1;         // col block (0..3) -> 48 cols

    const int row0 = blockIdx.x * 128;

    float acc[4][6][4];
#pragma unroll
    for (int mt = 0; mt < 4; mt++)
#pragma unroll
        for (int nt = 0; nt < 6; nt++)
#pragma unroll
            for (int i = 0; i < 4; i++) acc[mt][nt][i] = 0.0f;

    float4 xr[4];
    float4 wreg[3][2];

    // prefetch chunk 0
#pragma unroll
    for (int p = 0; p < 4; p++) {
        const int idx = tid + p * 256;
        const int r = idx >> 3, c4 = (idx & 7) * 4;
        xr[p] = *(const float4*)&x[(size_t)(row0 + r) * EE + c4];
    }
#pragma unroll
    for (int p = 0; p < 2; p++) {
        const int idx = tid + p * 256;
        const int r = idx >> 4, c4 = (idx & 15) * 4;
        wreg[0][p] = *(const float4*)&Wq[(size_t)r * HDD + c4];
        wreg[1][p] = *(const float4*)&Wk[(size_t)r * HDD + c4];
        wreg[2][p] = *(const float4*)&Wv[(size_t)r * HDD + c4];
    }

    for (int kbi = 0; kbi < 32; kbi++) {
        float* Xb = Xs + (kbi & 1) * XS_BUF;
        float* Wb = Ws + (kbi & 1) * WS_BUF;

        // store prefetched regs -> smem (convert to tf32)
#pragma unroll
        for (int p = 0; p < 4; p++) {
            const int idx = tid + p * 256;
            const int r = idx >> 3, c4 = (idx & 7) * 4;
            float* d = &Xb[r * XS_STRIDE + c4];
            d[0] = f2tff(xr[p].x); d[1] = f2tff(xr[p].y);
            d[2] = f2tff(xr[p].z); d[3] = f2tff(xr[p].w);
        }
#pragma unroll
        for (int w = 0; w < 3; w++)
#pragma unroll
            for (int p = 0; p < 2; p++) {
                const int idx = tid + p * 256;
                const int r = idx >> 4, c4 = (idx & 15) * 4;
                float* d = &Wb[r * WS3_STRIDE + w * 64 + c4];
                d[0] = f2tff(wreg[w][p].x); d[1] = f2tff(wreg[w][p].y);
                d[2] = f2tff(wreg[w][p].z); d[3] = f2tff(wreg[w][p].w);
            }

        // prefetch next chunk
        if (kbi < 31) {
            const int kb = (kbi + 1) * 32;
#pragma unroll
            for (int p = 0; p < 4; p++) {
                const int idx = tid + p * 256;
                const int r = idx >> 3, c4 = (idx & 7) * 4;
                xr[p] = *(const float4*)&x[(size_t)(row0 + r) * EE + kb + c4];
            }
#pragma unroll
            for (int p = 0; p < 2; p++) {
                const int idx = tid + p * 256;
                const int r = idx >> 4, c4 = (idx & 15) * 4;
                wreg[0][p] = *(const float4*)&Wq[(size_t)(kb + r) * HDD + c4];
                wreg[1][p] = *(const float4*)&Wk[(size_t)(kb + r) * HDD + c4];
                wreg[2][p] = *(const float4*)&Wv[(size_t)(kb + r) * HDD + c4];
            }
        }
        __syncthreads();   // single barrier per chunk (double-buffered smem)

#pragma unroll
        for (int ks = 0; ks < 4; ks++) {
            const int k0 = ks * 8;
            uint32_t a[4][4];
#pragma unroll
            for (int mt = 0; mt < 4; mt++) {
                const int r = wr * 64 + mt * 16 + gp;
                a[mt][0] = __float_as_uint(Xb[r * XS_STRIDE + k0 + qd]);
                a[mt][1] = __float_as_uint(Xb[(r + 8) * XS_STRIDE + k0 + qd]);
                a[mt][2] = __float_as_uint(Xb[r * XS_STRIDE + k0 + qd + 4]);
                a[mt][3] = __float_as_uint(Xb[(r + 8) * XS_STRIDE + k0 + qd + 4]);
            }
#pragma unroll
            for (int nt = 0; nt < 6; nt++) {
                uint32_t b[2];
                const int n = wc * 48 + nt * 8 + gp;
                b[0] = __float_as_uint(Wb[(k0 + qd) * WS3_STRIDE + n]);
                b[1] = __float_as_uint(Wb[(k0 + qd + 4) * WS3_STRIDE + n]);
#pragma unroll
                for (int mt = 0; mt < 4; mt++) mma8(acc[mt][nt], a[mt], b);
            }
        }
    }

    // epilogue: route each 8-col block to q/k/v head, pre-round to tf32
#pragma unroll
    for (int mt = 0; mt < 4; mt++) {
#pragma unroll
        for (int nt = 0; nt < 6; nt++) {
            const int r = row0 + wr * 64 + mt * 16 + gp;
            const int col192 = wc * 48 + nt * 8 + 2 * qd;
            float* outp = (col192 < 64) ? g_q : (col192 < 128) ? g_k : g_v;
            const int c = col192 & 63;
            *(float2*)&outp[(size_t)r * HDD + c] =
                make_float2(f2tff(acc[mt][nt][0]), f2tff(acc[mt][nt][1]));
            *(float2*)&outp[(size_t)(r + 8) * HDD + c] =
                make_float2(f2tff(acc[mt][nt][2]), f2tff(acc[mt][nt][3]));
        }
    }
}

// ---------------------------------------------------------------------------
// Stage 2: split-kv causal flash attention, base-2 softmax domain.
// Q pre-scaled by SCALE*log2e at load -> S is already in exp2 units:
// no per-element scale multiply, exp = single ex2.approx.
// grid (40, 8), block 256, 2 CTAs/SM. K/V register-prefetched.
// ---------------------------------------------------------------------------
#define QS 68                                  // smem row stride (floats)
#define ATTN_SMEM_BYTES ((128 * QS + 64 * QS + 64 * QS + 128 * QS) * 4)  // 104448

__global__ __launch_bounds__(256, 2) void attn_kernel(float* __restrict__ out)
{
    extern __shared__ float sm[];
    float* Qs = sm;                  // 128 x 64
    float* Ks = Qs + 128 * QS;       // 64 x 64
    float* Vs = Ks + 64 * QS;        // 64 x 64
    float* Ps = Vs + 64 * QS;        // 128 x 64

    const int tid  = threadIdx.x;
    const int warp = tid >> 5;
    const int lane = tid & 31;
    const int qd   = lane & 3;
    const int gp   = lane >> 2;
    const int b    = blockIdx.y;

    // map blockIdx.x -> (qt, chunk)
    int xx = blockIdx.x, qt = 0, ck = 0;
    for (qt = 0; qt < 16; qt++) {
        const int n = (qt + 4) >> 2;          // ceil((qt+1)/4)
        if (xx < n) { ck = xx; break; }
        xx -= n;
    }
    const int nc = (qt + 4) >> 2;
    const int j0 = ck * 8;
    const int j1 = min(ck * 8 + 8, 2 * (qt + 1));

    const int ldr  = tid >> 4;            // 0..15
    const int ldc4 = (tid & 15) * 4;

    // load Q tile [128 x 64] -> smem, folding SCALE*log2e (re-round to tf32)
    {
        const float* qptr = g_q + ((size_t)b * TT + qt * 128) * HDD;
#pragma unroll
        for (int p = 0; p < 8; p++) {
            float4 v = *(const float4*)&qptr[(size_t)(ldr + p * 16) * HDD + ldc4];
            float* d = &Qs[(ldr + p * 16) * QS + ldc4];
            d[0] = f2tff(v.x * SCALE_LOG2E);
            d[1] = f2tff(v.y * SCALE_LOG2E);
            d[2] = f2tff(v.z * SCALE_LOG2E);
            d[3] = f2tff(v.w * SCALE_LOG2E);
        }
    }

    const int r0  = warp * 16 + gp;            // local row
    const int rg0 = qt * 128 + r0;             // global row

    float m0 = -1e30f, m1 = -1e30f, l0 = 0.0f, l1 = 0.0f;
    float o[8][4];
#pragma unroll
    for (int nt = 0; nt < 8; nt++)
#pragma unroll
        for (int i = 0; i < 4; i++) o[nt][i] = 0.0f;

    // prefetch first K/V tile into registers
    float4 kr[4], vr[4];
    {
        const float* kp = g_k + ((size_t)b * TT + j0 * 64) * HDD;
        const float* vp = g_v + ((size_t)b * TT + j0 * 64) * HDD;
#pragma unroll
        for (int p = 0; p < 4; p++) {
            kr[p] = *(const float4*)&kp[(size_t)(ldr + p * 16) * HDD + ldc4];
            vr[p] = *(const float4*)&vp[(size_t)(ldr + p * 16) * HDD + ldc4];
        }
    }

    for (int j64 = j0; j64 < j1; j64++) {
        __syncthreads();   // previous tile fully consumed (also orders Q store, iter 0)
#pragma unroll
        for (int p = 0; p < 4; p++) {
            *(float4*)&Ks[(ldr + p * 16) * QS + ldc4] = kr[p];
            *(float4*)&Vs[(ldr + p * 16) * QS + ldc4] = vr[p];
        }
        // issue next tile's loads now — latency hides under this tile's compute
        if (j64 + 1 < j1) {
            const float* kp = g_k + ((size_t)b * TT + (j64 + 1) * 64) * HDD;
            const float* vp = g_v + ((size_t)b * TT + (j64 + 1) * 64) * HDD;
#pragma unroll
            for (int p = 0; p < 4; p++) {
                kr[p] = *(const float4*)&kp[(size_t)(ldr + p * 16) * HDD + ldc4];
                vr[p] = *(const float4*)&vp[(size_t)(ldr + p * 16) * HDD + ldc4];
            }
        }
        __syncthreads();

        // S'[16 x 64] = Qscaled rows @ K^T   (already in exp2 units)
        float s[8][4];
#pragma unroll
        for (int nt = 0; nt < 8; nt++)
#pragma unroll
            for (int i = 0; i < 4; i++) s[nt][i] = 0.0f;

#pragma unroll
        for (int ks = 0; ks < 8; ks++) {
            const int k0 = ks * 8;
            uint32_t a[4];
            a[0] = __float_as_uint(Qs[r0 * QS + k0 + qd]);
            a[1] = __float_as_uint(Qs[(r0 + 8) * QS + k0 + qd]);
            a[2] = __float_as_uint(Qs[r0 * QS + k0 + qd + 4]);
            a[3] = __float_as_uint(Qs[(r0 + 8) * QS + k0 + qd + 4]);
#pragma unroll
            for (int nt = 0; nt < 8; nt++) {
                uint32_t bb[2];
                const int n = nt * 8 + gp;
                bb[0] = __float_as_uint(Ks[n * QS + k0 + qd]);
                bb[1] = __float_as_uint(Ks[n * QS + k0 + qd + 4]);
                mma8(s[nt], a, bb);
            }
        }

        // causal mask (only diagonal tiles)
        if (j64 >= 2 * qt) {
#pragma unroll
            for (int nt = 0; nt < 8; nt++) {
                const int c = j64 * 64 + nt * 8 + 2 * qd;
                if (c     > rg0)     s[nt][0] = -1e30f;
                if (c + 1 > rg0)     s[nt][1] = -1e30f;
                if (c     > rg0 + 8) s[nt][2] = -1e30f;
                if (c + 1 > rg0 + 8) s[nt][3] = -1e30f;
            }
        }

        float mx0 = -1e30f, mx1 = -1e30f;
#pragma unroll
        for (int nt = 0; nt < 8; nt++) {
            mx0 = fmaxf(mx0, fmaxf(s[nt][0], s[nt][1]));
            mx1 = fmaxf(mx1, fmaxf(s[nt][2], s[nt][3]));
        }
        mx0 = fmaxf(mx0, __shfl_xor_sync(0xffffffffu, mx0, 1));
        mx0 = fmaxf(mx0, __shfl_xor_sync(0xffffffffu, mx0, 2));
        mx1 = fmaxf(mx1, __shfl_xor_sync(0xffffffffu, mx1, 1));
        mx1 = fmaxf(mx1, __shfl_xor_sync(0xffffffffu, mx1, 2));

        const float nm0 = fmaxf(m0, mx0);
        const float nm1 = fmaxf(m1, mx1);
        const float a0 = ex2(m0 - nm0);
        const float a1 = ex2(m1 - nm1);
        m0 = nm0; m1 = nm1;

        float sum0 = 0.0f, sum1 = 0.0f;
#pragma unroll
        for (int nt = 0; nt < 8; nt++) {
            s[nt][0] = ex2(s[nt][0] - nm0);
            s[nt][1] = ex2(s[nt][1] - nm0);
            s[nt][2] = ex2(s[nt][2] - nm1);
            s[nt][3] = ex2(s[nt][3] - nm1);
            sum0 += s[nt][0] + s[nt][1];
            sum1 += s[nt][2] + s[nt][3];
        }
        sum0 += __shfl_xor_sync(0xffffffffu, sum0, 1);
        sum0 += __shfl_xor_sync(0xffffffffu, sum0, 2);
        sum1 += __shfl_xor_sync(0xffffffffu, sum1, 1);
        sum1 += __shfl_xor_sync(0xffffffffu, sum1, 2);
        l0 = l0 * a0 + sum0;
        l1 = l1 * a1 + sum1;

#pragma unroll
        for (int nt = 0; nt < 8; nt++) {
            o[nt][0] *= a0; o[nt][1] *= a0;
            o[nt][2] *= a1; o[nt][3] *= a1;
        }

        // stage P (tf32) into warp-private smem rows
#pragma unroll
        for (int nt = 0; nt < 8; nt++) {
            const int c = nt * 8 + 2 * qd;
            *(float2*)&Ps[r0 * QS + c]       = make_float2(f2tff(s[nt][0]), f2tff(s[nt][1]));
            *(float2*)&Ps[(r0 + 8) * QS + c] = make_float2(f2tff(s[nt][2]), f2tff(s[nt][3]));
        }
        __syncwarp();

        // O += P[16 x 64] @ V[64 x 64]
#pragma unroll
        for (int ks = 0; ks < 8; ks++) {
            const int k0 = ks * 8;
            uint32_t a[4];
            a[0] = __float_as_uint(Ps[r0 * QS + k0 + qd]);
            a[1] = __float_as_uint(Ps[(r0 + 8) * QS + k0 + qd]);
            a[2] = __float_as_uint(Ps[r0 * QS + k0 + qd + 4]);
            a[3] = __float_as_uint(Ps[(r0 + 8) * QS + k0 + qd + 4]);
#pragma unroll
            for (int nt = 0; nt < 8; nt++) {
                uint32_t bb[2];
                const int n = nt * 8 + gp;
                bb[0] = __float_as_uint(Vs[(k0 + qd) * QS + n]);
                bb[1] = __float_as_uint(Vs[(k0 + qd + 4) * QS + n]);
                mma8(o[nt], a, bb);
            }
        }
    }

    if (nc == 1) {
        const float inv0 = 1.0f / l0;
        const float inv1 = 1.0f / l1;
        float* op = out + ((size_t)b * TT + qt * 128) * HDD;
#pragma unroll
        for (int nt = 0; nt < 8; nt++) {
            const int c = nt * 8 + 2 * qd;
            *(float2*)&op[(size_t)r0 * HDD + c]       = make_float2(o[nt][0] * inv0, o[nt][1] * inv0);
            *(float2*)&op[(size_t)(r0 + 8) * HDD + c] = make_float2(o[nt][2] * inv1, o[nt][3] * inv1);
        }
    } else {
        const int pidx = (b * 16 + qt) * 4 + ck;
        float* po = g_po + (size_t)pidx * 128 * HDD;
#pragma unroll
        for (int nt = 0; nt < 8; nt++) {
            const int c = nt * 8 + 2 * qd;
            *(float2*)&po[(size_t)r0 * HDD + c]       = make_float2(o[nt][0], o[nt][1]);
            *(float2*)&po[(size_t)(r0 + 8) * HDD + c] = make_float2(o[nt][2], o[nt][3]);
        }
        if (qd == 0) {
            // m stored in base-2 domain; combine uses ex2 consistently
            g_pm[pidx * 128 + r0]     = m0;
            g_pm[pidx * 128 + r0 + 8] = m1;
            g_pl[pidx * 128 + r0]     = l0;
            g_pl[pidx * 128 + r0 + 8] = l1;
        }
    }
}

// ---------------------------------------------------------------------------
// Stage 3: combine split-kv partials (base-2 domain). grid (12, 8).
// ---------------------------------------------------------------------------
__global__ __launch_bounds__(256) void combine_kernel(float* __restrict__ out)
{
    const int qt  = blockIdx.x + 4;
    const int b   = blockIdx.y;
    const int nc  = (qt + 4) >> 2;       // 2..4
    const int tid = threadIdx.x;
    const int r    = tid >> 1;           // 0..127
    const int half = (tid & 1) * 32;
    const int base = (b * 16 + qt) * 4;

    float m[4], l[4], w[4];
    float mstar = -1e30f;
#pragma unroll 4
    for (int c = 0; c < nc; c++) {
        m[c] = g_pm[(base + c) * 128 + r];
        l[c] = g_pl[(base + c) * 128 + r];
        mstar = fmaxf(mstar, m[c]);
    }
    float lstar = 0.0f;
#pragma unroll 4
    for (int c = 0; c < nc; c++) {
        float e;
        asm("ex2.approx.f32 %0, %1;" : "=f"(e) : "f"(m[c] - mstar));
        w[c] = e;
        lstar += e * l[c];
    }
    const float inv = 1.0f / lstar;
#pragma unroll 4
    for (int c = 0; c < nc; c++) w[c] *= inv;

    float* op = out + ((size_t)b * TT + qt * 128 + r) * HDD + half;
#pragma unroll
    for (int g = 0; g < 8; g++) {
        float4 acc = make_float4(0.f, 0.f, 0.f, 0.f);
#pragma unroll 4
        for (int c = 0; c < nc; c++) {
            const float4 v = *(const float4*)&g_po[(size_t)(base + c) * 128 * HDD + r * HDD + half + g * 4];
            acc.x += w[c] * v.x; acc.y += w[c] * v.y;
            acc.z += w[c] * v.z; acc.w += w[c] * v.w;
        }
        *(float4*)&op[g * 4] = acc;
    }
}

// ---------------------------------------------------------------------------
// launch
// ---------------------------------------------------------------------------
extern "C" void kernel_launch(void* const* d_in, const int* in_sizes, int n_in,
                              void* d_out, int out_size)
{
    const float* x  = (const float*)d_in[0];
    const float* Wq = (const float*)d_in[1];
    const float* Wk = (const float*)d_in[2];
    const float* Wv = (const float*)d_in[3];
    float* out = (float*)d_out;

    cudaFuncSetAttribute(qkv_kernel, cudaFuncAttributeMaxDynamicSharedMemorySize,
                         QKV_SMEM_BYTES);
    qkv_kernel<<<MM / 128, 256, QKV_SMEM_BYTES>>>(x, Wq, Wk, Wv);

    cudaFuncSetAttribute(attn_kernel, cudaFuncAttributeMaxDynamicSharedMemorySize,
                         ATTN_SMEM_BYTES);
    attn_kernel<<<dim3(40, 8), 256, ATTN_SMEM_BYTES>>>(out);

    combine_kernel<<<dim3(12, 8), 256>>>(out);
}

// round 10
// speedup vs baseline: 1.5340x; 1.5340x over previous
#include <cuda_runtime.h>
#include <cstdint>

// Problem constants
#define BB 8
#define TT 2048
#define EE 1024
#define HDD 64
#define MM (BB * TT)          // 16384 rows
// SCALE * log2(e): folded into Q so softmax runs in base-2 domain
#define SCALE_LOG2E 0.1803368801111601f

// Scratch for q,k,v projections (stored pre-rounded to tf32), 4 MB each
__device__ float g_q[MM * HDD];
__device__ float g_k[MM * HDD];
__device__ float g_v[MM * HDD];
// Split-kv partials: [b][qt][chunk] x (128 rows x 64 cols) + per-row m,l
__device__ float g_po[BB * 16 * 4 * 128 * HDD];
__device__ float g_pm[BB * 16 * 4 * 128];
__device__ float g_pl[BB * 16 * 4 * 128];

// ---------------------------------------------------------------------------
// helpers
// ---------------------------------------------------------------------------
__device__ __forceinline__ float f2tff(float x) {
    uint32_t u;
    asm("cvt.rna.tf32.f32 %0, %1;" : "=r"(u) : "f"(x));
    return __uint_as_float(u);
}

__device__ __forceinline__ float ex2(float x) {
    float r;
    asm("ex2.approx.f32 %0, %1;" : "=f"(r) : "f"(x));
    return r;
}

__device__ __forceinline__ void mma8(float* c, const uint32_t* a, const uint32_t* b) {
    asm volatile(
        "mma.sync.aligned.m16n8k8.row.col.f32.tf32.tf32.f32 "
        "{%0,%1,%2,%3}, {%4,%5,%6,%7}, {%8,%9}, {%0,%1,%2,%3};"
        : "+f"(c[0]), "+f"(c[1]), "+f"(c[2]), "+f"(c[3])
        : "r"(a[0]), "r"(a[1]), "r"(a[2]), "r"(a[3]), "r"(b[0]), "r"(b[1]));
}

// ---------------------------------------------------------------------------
// Stage 1: fused QKV projection (exact R2 config — measured 54.7us clean).
// CTA tile 128 rows x 192 cols (Q|K|V heads). grid 128, block 256.
// Register-double-buffered smem, ONE __syncthreads per 32-wide k-chunk.
// ---------------------------------------------------------------------------
#define XS_STRIDE 36          // 36 % 32 == 4 -> conflict-friendly
#define WS3_STRIDE 196        // 196 % 32 == 4
#define XS_BUF (128 * XS_STRIDE)
#define WS_BUF (32 * WS3_STRIDE)
#define QKV_SMEM_BYTES ((2 * XS_BUF + 2 * WS_BUF) * 4)   // 87040

__global__ __launch_bounds__(256) void qkv_kernel(
    const float* __restrict__ x,
    const float* __restrict__ Wq,
    const float* __restrict__ Wk,
    const float* __restrict__ Wv)
{
    extern __shared__ float sm[];
    float* Xs = sm;                     // [2][128*36]
    float* Ws = sm + 2 * XS_BUF;        // [2][32*196]

    const int tid  = threadIdx.x;
    const int warp = tid >> 5;
    const int lane = tid & 31;
    const int qd   = lane & 3;
    const int gp   = lane >> 2;
    const int wr   = warp & 1;          // row half (0/1) -> 64 rows
    const int wc   = warp >> 1;         // col block (0..3) -> 48 cols

    const int row0 = blockIdx.x * 128;

    float acc[4][6][4];
#pragma unroll
    for (int mt = 0; mt < 4; mt++)
#pragma unroll
        for (int nt = 0; nt < 6; nt++)
#pragma unroll
            for (int i = 0; i < 4; i++) acc[mt][nt][i] = 0.0f;

    float4 xr[4];
    float4 wreg[3][2];

    // prefetch chunk 0
#pragma unroll
    for (int p = 0; p < 4; p++) {
        const int idx = tid + p * 256;
        const int r = idx >> 3, c4 = (idx & 7) * 4;
        xr[p] = *(const float4*)&x[(size_t)(row0 + r) * EE + c4];
    }
#pragma unroll
    for (int p = 0; p < 2; p++) {
        const int idx = tid + p * 256;
        const int r = idx >> 4, c4 = (idx & 15) * 4;
        wreg[0][p] = *(const float4*)&Wq[(size_t)r * HDD + c4];
        wreg[1][p] = *(const float4*)&Wk[(size_t)r * HDD + c4];
        wreg[2][p] = *(const float4*)&Wv[(size_t)r * HDD + c4];
    }

    for (int kbi = 0; kbi < 32; kbi++) {
        float* Xb = Xs + (kbi & 1) * XS_BUF;
        float* Wb = Ws + (kbi & 1) * WS_BUF;

        // store prefetched regs -> smem (convert to tf32)
#pragma unroll
        for (int p = 0; p < 4; p++) {
            const int idx = tid + p * 256;
            const int r = idx >> 3, c4 = (idx & 7) * 4;
            float* d = &Xb[r * XS_STRIDE + c4];
            d[0] = f2tff(xr[p].x); d[1] = f2tff(xr[p].y);
            d[2] = f2tff(xr[p].z); d[3] = f2tff(xr[p].w);
        }
#pragma unroll
        for (int w = 0; w < 3; w++)
#pragma unroll
            for (int p = 0; p < 2; p++) {
                const int idx = tid + p * 256;
                const int r = idx >> 4, c4 = (idx & 15) * 4;
                float* d = &Wb[r * WS3_STRIDE + w * 64 + c4];
                d[0] = f2tff(wreg[w][p].x); d[1] = f2tff(wreg[w][p].y);
                d[2] = f2tff(wreg[w][p].z); d[3] = f2tff(wreg[w][p].w);
            }

        // prefetch next chunk
        if (kbi < 31) {
            const int kb = (kbi + 1) * 32;
#pragma unroll
            for (int p = 0; p < 4; p++) {
                const int idx = tid + p * 256;
                const int r = idx >> 3, c4 = (idx & 7) * 4;
                xr[p] = *(const float4*)&x[(size_t)(row0 + r) * EE + kb + c4];
            }
#pragma unroll
            for (int p = 0; p < 2; p++) {
                const int idx = tid + p * 256;
                const int r = idx >> 4, c4 = (idx & 15) * 4;
                wreg[0][p] = *(const float4*)&Wq[(size_t)(kb + r) * HDD + c4];
                wreg[1][p] = *(const float4*)&Wk[(size_t)(kb + r) * HDD + c4];
                wreg[2][p] = *(const float4*)&Wv[(size_t)(kb + r) * HDD + c4];
            }
        }
        __syncthreads();   // single barrier per chunk (double-buffered smem)

#pragma unroll
        for (int ks = 0; ks < 4; ks++) {
            const int k0 = ks * 8;
            uint32_t a[4][4];
#pragma unroll
            for (int mt = 0; mt < 4; mt++) {
                const int r = wr * 64 + mt * 16 + gp;
                a[mt][0] = __float_as_uint(Xb[r * XS_STRIDE + k0 + qd]);
                a[mt][1] = __float_as_uint(Xb[(r + 8) * XS_STRIDE + k0 + qd]);
                a[mt][2] = __float_as_uint(Xb[r * XS_STRIDE + k0 + qd + 4]);
                a[mt][3] = __float_as_uint(Xb[(r + 8) * XS_STRIDE + k0 + qd + 4]);
            }
#pragma unroll
            for (int nt = 0; nt < 6; nt++) {
                uint32_t b[2];
                const int n = wc * 48 + nt * 8 + gp;
                b[0] = __float_as_uint(Wb[(k0 + qd) * WS3_STRIDE + n]);
                b[1] = __float_as_uint(Wb[(k0 + qd + 4) * WS3_STRIDE + n]);
#pragma unroll
                for (int mt = 0; mt < 4; mt++) mma8(acc[mt][nt], a[mt], b);
            }
        }
    }

    // epilogue: route each 8-col block to q/k/v head, pre-round to tf32
#pragma unroll
    for (int mt = 0; mt < 4; mt++) {
#pragma unroll
        for (int nt = 0; nt < 6; nt++) {
            const int r = row0 + wr * 64 + mt * 16 + gp;
            const int col192 = wc * 48 + nt * 8 + 2 * qd;
            float* outp = (col192 < 64) ? g_q : (col192 < 128) ? g_k : g_v;
            const int c = col192 & 63;
            *(float2*)&outp[(size_t)r * HDD + c] =
                make_float2(f2tff(acc[mt][nt][0]), f2tff(acc[mt][nt][1]));
            *(float2*)&outp[(size_t)(r + 8) * HDD + c] =
                make_float2(f2tff(acc[mt][nt][2]), f2tff(acc[mt][nt][3]));
        }
    }
}

// ---------------------------------------------------------------------------
// Stage 2: split-kv causal flash attention, base-2 softmax domain.
// Q pre-scaled by SCALE*log2e at load -> S is already in exp2 units:
// no per-element scale multiply, exp = single ex2.approx.
// grid (40, 8), block 256, 2 CTAs/SM. K/V register-prefetched.
// ---------------------------------------------------------------------------
#define QS 68                                  // smem row stride (floats)
#define ATTN_SMEM_BYTES ((128 * QS + 64 * QS + 64 * QS + 128 * QS) * 4)  // 104448

__global__ __launch_bounds__(256, 2) void attn_kernel(float* __restrict__ out)
{
    extern __shared__ float sm[];
    float* Qs = sm;                  // 128 x 64
    float* Ks = Qs + 128 * QS;       // 64 x 64
    float* Vs = Ks + 64 * QS;        // 64 x 64
    float* Ps = Vs + 64 * QS;        // 128 x 64

    const int tid  = threadIdx.x;
    const int warp = tid >> 5;
    const int lane = tid & 31;
    const int qd   = lane & 3;
    const int gp   = lane >> 2;
    const int b    = blockIdx.y;

    // map blockIdx.x -> (qt, chunk)
    int xx = blockIdx.x, qt = 0, ck = 0;
    for (qt = 0; qt < 16; qt++) {
        const int n = (qt + 4) >> 2;          // ceil((qt+1)/4)
        if (xx < n) { ck = xx; break; }
        xx -= n;
    }
    const int nc = (qt + 4) >> 2;
    const int j0 = ck * 8;
    const int j1 = min(ck * 8 + 8, 2 * (qt + 1));

    const int ldr  = tid >> 4;            // 0..15
    const int ldc4 = (tid & 15) * 4;

    // load Q tile [128 x 64] -> smem, folding SCALE*log2e (re-round to tf32)
    {
        const float* qptr = g_q + ((size_t)b * TT + qt * 128) * HDD;
#pragma unroll
        for (int p = 0; p < 8; p++) {
            float4 v = *(const float4*)&qptr[(size_t)(ldr + p * 16) * HDD + ldc4];
            float* d = &Qs[(ldr + p * 16) * QS + ldc4];
            d[0] = f2tff(v.x * SCALE_LOG2E);
            d[1] = f2tff(v.y * SCALE_LOG2E);
            d[2] = f2tff(v.z * SCALE_LOG2E);
            d[3] = f2tff(v.w * SCALE_LOG2E);
        }
    }

    const int r0  = warp * 16 + gp;            // local row
    const int rg0 = qt * 128 + r0;             // global row

    float m0 = -1e30f, m1 = -1e30f, l0 = 0.0f, l1 = 0.0f;
    float o[8][4];
#pragma unroll
    for (int nt = 0; nt < 8; nt++)
#pragma unroll
        for (int i = 0; i < 4; i++) o[nt][i] = 0.0f;

    // prefetch first K/V tile into registers
    float4 kr[4], vr[4];
    {
        const float* kp = g_k + ((size_t)b * TT + j0 * 64) * HDD;
        const float* vp = g_v + ((size_t)b * TT + j0 * 64) * HDD;
#pragma unroll
        for (int p = 0; p < 4; p++) {
            kr[p] = *(const float4*)&kp[(size_t)(ldr + p * 16) * HDD + ldc4];
            vr[p] = *(const float4*)&vp[(size_t)(ldr + p * 16) * HDD + ldc4];
        }
    }

    for (int j64 = j0; j64 < j1; j64++) {
        __syncthreads();   // previous tile fully consumed (also orders Q store, iter 0)
#pragma unroll
        for (int p = 0; p < 4; p++) {
            *(float4*)&Ks[(ldr + p * 16) * QS + ldc4] = kr[p];
            *(float4*)&Vs[(ldr + p * 16) * QS + ldc4] = vr[p];
        }
        // issue next tile's loads now — latency hides under this tile's compute
        if (j64 + 1 < j1) {
            const float* kp = g_k + ((size_t)b * TT + (j64 + 1) * 64) * HDD;
            const float* vp = g_v + ((size_t)b * TT + (j64 + 1) * 64) * HDD;
#pragma unroll
            for (int p = 0; p < 4; p++) {
                kr[p] = *(const float4*)&kp[(size_t)(ldr + p * 16) * HDD + ldc4];
                vr[p] = *(const float4*)&vp[(size_t)(ldr + p * 16) * HDD + ldc4];
            }
        }
        __syncthreads();

        // S'[16 x 64] = Qscaled rows @ K^T   (already in exp2 units)
        float s[8][4];
#pragma unroll
        for (int nt = 0; nt < 8; nt++)
#pragma unroll
            for (int i = 0; i < 4; i++) s[nt][i] = 0.0f;

#pragma unroll
        for (int ks = 0; ks < 8; ks++) {
            const int k0 = ks * 8;
            uint32_t a[4];
            a[0] = __float_as_uint(Qs[r0 * QS + k0 + qd]);
            a[1] = __float_as_uint(Qs[(r0 + 8) * QS + k0 + qd]);
            a[2] = __float_as_uint(Qs[r0 * QS + k0 + qd + 4]);
            a[3] = __float_as_uint(Qs[(r0 + 8) * QS + k0 + qd + 4]);
#pragma unroll
            for (int nt = 0; nt < 8; nt++) {
                uint32_t bb[2];
                const int n = nt * 8 + gp;
                bb[0] = __float_as_uint(Ks[n * QS + k0 + qd]);
                bb[1] = __float_as_uint(Ks[n * QS + k0 + qd + 4]);
                mma8(s[nt], a, bb);
            }
        }

        // causal mask (only diagonal tiles)
        if (j64 >= 2 * qt) {
#pragma unroll
            for (int nt = 0; nt < 8; nt++) {
                const int c = j64 * 64 + nt * 8 + 2 * qd;
                if (c     > rg0)     s[nt][0] = -1e30f;
                if (c + 1 > rg0)     s[nt][1] = -1e30f;
                if (c     > rg0 + 8) s[nt][2] = -1e30f;
                if (c + 1 > rg0 + 8) s[nt][3] = -1e30f;
            }
        }

        float mx0 = -1e30f, mx1 = -1e30f;
#pragma unroll
        for (int nt = 0; nt < 8; nt++) {
            mx0 = fmaxf(mx0, fmaxf(s[nt][0], s[nt][1]));
            mx1 = fmaxf(mx1, fmaxf(s[nt][2], s[nt][3]));
        }
        mx0 = fmaxf(mx0, __shfl_xor_sync(0xffffffffu, mx0, 1));
        mx0 = fmaxf(mx0, __shfl_xor_sync(0xffffffffu, mx0, 2));
        mx1 = fmaxf(mx1, __shfl_xor_sync(0xffffffffu, mx1, 1));
        mx1 = fmaxf(mx1, __shfl_xor_sync(0xffffffffu, mx1, 2));

        const float nm0 = fmaxf(m0, mx0);
        const float nm1 = fmaxf(m1, mx1);
        const float a0 = ex2(m0 - nm0);
        const float a1 = ex2(m1 - nm1);
        m0 = nm0; m1 = nm1;

        float sum0 = 0.0f, sum1 = 0.0f;
#pragma unroll
        for (int nt = 0; nt < 8; nt++) {
            s[nt][0] = ex2(s[nt][0] - nm0);
            s[nt][1] = ex2(s[nt][1] - nm0);
            s[nt][2] = ex2(s[nt][2] - nm1);
            s[nt][3] = ex2(s[nt][3] - nm1);
            sum0 += s[nt][0] + s[nt][1];
            sum1 += s[nt][2] + s[nt][3];
        }
        sum0 += __shfl_xor_sync(0xffffffffu, sum0, 1);
        sum0 += __shfl_xor_sync(0xffffffffu, sum0, 2);
        sum1 += __shfl_xor_sync(0xffffffffu, sum1, 1);
        sum1 += __shfl_xor_sync(0xffffffffu, sum1, 2);
        l0 = l0 * a0 + sum0;
        l1 = l1 * a1 + sum1;

#pragma unroll
        for (int nt = 0; nt < 8; nt++) {
            o[nt][0] *= a0; o[nt][1] *= a0;
            o[nt][2] *= a1; o[nt][3] *= a1;
        }

        // stage P (tf32) into warp-private smem rows
#pragma unroll
        for (int nt = 0; nt < 8; nt++) {
            const int c = nt * 8 + 2 * qd;
            *(float2*)&Ps[r0 * QS + c]       = make_float2(f2tff(s[nt][0]), f2tff(s[nt][1]));
            *(float2*)&Ps[(r0 + 8) * QS + c] = make_float2(f2tff(s[nt][2]), f2tff(s[nt][3]));
        }
        __syncwarp();

        // O += P[16 x 64] @ V[64 x 64]
#pragma unroll
        for (int ks = 0; ks < 8; ks++) {
            const int k0 = ks * 8;
            uint32_t a[4];
            a[0] = __float_as_uint(Ps[r0 * QS + k0 + qd]);
            a[1] = __float_as_uint(Ps[(r0 + 8) * QS + k0 + qd]);
            a[2] = __float_as_uint(Ps[r0 * QS + k0 + qd + 4]);
            a[3] = __float_as_uint(Ps[(r0 + 8) * QS + k0 + qd + 4]);
#pragma unroll
            for (int nt = 0; nt < 8; nt++) {
                uint32_t bb[2];
                const int n = nt * 8 + gp;
                bb[0] = __float_as_uint(Vs[(k0 + qd) * QS + n]);
                bb[1] = __float_as_uint(Vs[(k0 + qd + 4) * QS + n]);
                mma8(o[nt], a, bb);
            }
        }
    }

    if (nc == 1) {
        const float inv0 = 1.0f / l0;
        const float inv1 = 1.0f / l1;
        float* op = out + ((size_t)b * TT + qt * 128) * HDD;
#pragma unroll
        for (int nt = 0; nt < 8; nt++) {
            const int c = nt * 8 + 2 * qd;
            *(float2*)&op[(size_t)r0 * HDD + c]       = make_float2(o[nt][0] * inv0, o[nt][1] * inv0);
            *(float2*)&op[(size_t)(r0 + 8) * HDD + c] = make_float2(o[nt][2] * inv1, o[nt][3] * inv1);
        }
    } else {
        const int pidx = (b * 16 + qt) * 4 + ck;
        float* po = g_po + (size_t)pidx * 128 * HDD;
#pragma unroll
        for (int nt = 0; nt < 8; nt++) {
            const int c = nt * 8 + 2 * qd;
            *(float2*)&po[(size_t)r0 * HDD + c]       = make_float2(o[nt][0], o[nt][1]);
            *(float2*)&po[(size_t)(r0 + 8) * HDD + c] = make_float2(o[nt][2], o[nt][3]);
        }
        if (qd == 0) {
            // m stored in base-2 domain; combine uses ex2 consistently
            g_pm[pidx * 128 + r0]     = m0;
            g_pm[pidx * 128 + r0 + 8] = m1;
            g_pl[pidx * 128 + r0]     = l0;
            g_pl[pidx * 128 + r0 + 8] = l1;
        }
    }
}

// ---------------------------------------------------------------------------
// Stage 3: combine split-kv partials (base-2 domain). grid (12, 8).
// ---------------------------------------------------------------------------
__global__ __launch_bounds__(256) void combine_kernel(float* __restrict__ out)
{
    const int qt  = blockIdx.x + 4;
    const int b   = blockIdx.y;
    const int nc  = (qt + 4) >> 2;       // 2..4
    const int tid = threadIdx.x;
    const int r    = tid >> 1;           // 0..127
    const int half = (tid & 1) * 32;
    const int base = (b * 16 + qt) * 4;

    float m[4], l[4], w[4];
    float mstar = -1e30f;
#pragma unroll 4
    for (int c = 0; c < nc; c++) {
        m[c] = g_pm[(base + c) * 128 + r];
        l[c] = g_pl[(base + c) * 128 + r];
        mstar = fmaxf(mstar, m[c]);
    }
    float lstar = 0.0f;
#pragma unroll 4
    for (int c = 0; c < nc; c++) {
        float e;
        asm("ex2.approx.f32 %0, %1;" : "=f"(e) : "f"(m[c] - mstar));
        w[c] = e;
        lstar += e * l[c];
    }
    const float inv = 1.0f / lstar;
#pragma unroll 4
    for (int c = 0; c < nc; c++) w[c] *= inv;

    float* op = out + ((size_t)b * TT + qt * 128 + r) * HDD + half;
#pragma unroll
    for (int g = 0; g < 8; g++) {
        float4 acc = make_float4(0.f, 0.f, 0.f, 0.f);
#pragma unroll 4
        for (int c = 0; c < nc; c++) {
            const float4 v = *(const float4*)&g_po[(size_t)(base + c) * 128 * HDD + r * HDD + half + g * 4];
            acc.x += w[c] * v.x; acc.y += w[c] * v.y;
            acc.z += w[c] * v.z; acc.w += w[c] * v.w;
        }
        *(float4*)&op[g * 4] = acc;
    }
}

// ---------------------------------------------------------------------------
// launch
// ---------------------------------------------------------------------------
extern "C" void kernel_launch(void* const* d_in, const int* in_sizes, int n_in,
                              void* d_out, int out_size)
{
    const float* x  = (const float*)d_in[0];
    const float* Wq = (const float*)d_in[1];
    const float* Wk = (const float*)d_in[2];
    const float* Wv = (const float*)d_in[3];
    float* out = (float*)d_out;

    cudaFuncSetAttribute(qkv_kernel, cudaFuncAttributeMaxDynamicSharedMemorySize,
                         QKV_SMEM_BYTES);
    qkv_kernel<<<MM / 128, 256, QKV_SMEM_BYTES>>>(x, Wq, Wk, Wv);

    cudaFuncSetAttribute(attn_kernel, cudaFuncAttributeMaxDynamicSharedMemorySize,
                         ATTN_SMEM_BYTES);
    attn_kernel<<<dim3(40, 8), 256, ATTN_SMEM_BYTES>>>(out);

    combine_kernel<<<dim3(12, 8), 256>>>(out);
}

// round 11
// speedup vs baseline: 1.5562x; 1.0145x over previous
#include <cuda_runtime.h>
#include <cstdint>

// Problem constants
#define BB 8
#define TT 2048
#define EE 1024
#define HDD 64
#define MM (BB * TT)          // 16384 rows
// SCALE * log2(e): folded into Q so softmax runs in base-2 domain
#define SCALE_LOG2E 0.1803368801111601f

// Scratch for q,k,v projections (stored pre-rounded to tf32), 4 MB each
__device__ float g_q[MM * HDD];
__device__ float g_k[MM * HDD];
__device__ float g_v[MM * HDD];
// Split-kv partials: [b][qt][chunk] x (128 rows x 64 cols) + per-row m,l
__device__ float g_po[BB * 16 * 4 * 128 * HDD];
__device__ float g_pm[BB * 16 * 4 * 128];
__device__ float g_pl[BB * 16 * 4 * 128];

// ---------------------------------------------------------------------------
// helpers
// ---------------------------------------------------------------------------
__device__ __forceinline__ float f2tff(float x) {
    uint32_t u;
    asm("cvt.rna.tf32.f32 %0, %1;" : "=r"(u) : "f"(x));
    return __uint_as_float(u);
}

__device__ __forceinline__ float ex2(float x) {
    float r;
    asm("ex2.approx.f32 %0, %1;" : "=f"(r) : "f"(x));
    return r;
}

__device__ __forceinline__ void mma8(float* c, const uint32_t* a, const uint32_t* b) {
    asm volatile(
        "mma.sync.aligned.m16n8k8.row.col.f32.tf32.tf32.f32 "
        "{%0,%1,%2,%3}, {%4,%5,%6,%7}, {%8,%9}, {%0,%1,%2,%3};"
        : "+f"(c[0]), "+f"(c[1]), "+f"(c[2]), "+f"(c[3])
        : "r"(a[0]), "r"(a[1]), "r"(a[2]), "r"(a[3]), "r"(b[0]), "r"(b[1]));
}

// ---------------------------------------------------------------------------
// Stage 1: fused QKV projection (exact R2 config — measured ~55us clean).
// CTA tile 128 rows x 192 cols (Q|K|V heads). grid 128, block 256.
// ---------------------------------------------------------------------------
#define XS_STRIDE 36
#define WS3_STRIDE 196
#define XS_BUF (128 * XS_STRIDE)
#define WS_BUF (32 * WS3_STRIDE)
#define QKV_SMEM_BYTES ((2 * XS_BUF + 2 * WS_BUF) * 4)   // 87040

__global__ __launch_bounds__(256) void qkv_kernel(
    const float* __restrict__ x,
    const float* __restrict__ Wq,
    const float* __restrict__ Wk,
    const float* __restrict__ Wv)
{
    extern __shared__ float sm[];
    float* Xs = sm;
    float* Ws = sm + 2 * XS_BUF;

    const int tid  = threadIdx.x;
    const int warp = tid >> 5;
    const int lane = tid & 31;
    const int qd   = lane & 3;
    const int gp   = lane >> 2;
    const int wr   = warp & 1;
    const int wc   = warp >> 1;

    const int row0 = blockIdx.x * 128;

    float acc[4][6][4];
#pragma unroll
    for (int mt = 0; mt < 4; mt++)
#pragma unroll
        for (int nt = 0; nt < 6; nt++)
#pragma unroll
            for (int i = 0; i < 4; i++) acc[mt][nt][i] = 0.0f;

    float4 xr[4];
    float4 wreg[3][2];

#pragma unroll
    for (int p = 0; p < 4; p++) {
        const int idx = tid + p * 256;
        const int r = idx >> 3, c4 = (idx & 7) * 4;
        xr[p] = *(const float4*)&x[(size_t)(row0 + r) * EE + c4];
    }
#pragma unroll
    for (int p = 0; p < 2; p++) {
        const int idx = tid + p * 256;
        const int r = idx >> 4, c4 = (idx & 15) * 4;
        wreg[0][p] = *(const float4*)&Wq[(size_t)r * HDD + c4];
        wreg[1][p] = *(const float4*)&Wk[(size_t)r * HDD + c4];
        wreg[2][p] = *(const float4*)&Wv[(size_t)r * HDD + c4];
    }

    for (int kbi = 0; kbi < 32; kbi++) {
        float* Xb = Xs + (kbi & 1) * XS_BUF;
        float* Wb = Ws + (kbi & 1) * WS_BUF;

#pragma unroll
        for (int p = 0; p < 4; p++) {
            const int idx = tid + p * 256;
            const int r = idx >> 3, c4 = (idx & 7) * 4;
            float* d = &Xb[r * XS_STRIDE + c4];
            d[0] = f2tff(xr[p].x); d[1] = f2tff(xr[p].y);
            d[2] = f2tff(xr[p].z); d[3] = f2tff(xr[p].w);
        }
#pragma unroll
        for (int w = 0; w < 3; w++)
#pragma unroll
            for (int p = 0; p < 2; p++) {
                const int idx = tid + p * 256;
                const int r = idx >> 4, c4 = (idx & 15) * 4;
                float* d = &Wb[r * WS3_STRIDE + w * 64 + c4];
                d[0] = f2tff(wreg[w][p].x); d[1] = f2tff(wreg[w][p].y);
                d[2] = f2tff(wreg[w][p].z); d[3] = f2tff(wreg[w][p].w);
            }

        if (kbi < 31) {
            const int kb = (kbi + 1) * 32;
#pragma unroll
            for (int p = 0; p < 4; p++) {
                const int idx = tid + p * 256;
                const int r = idx >> 3, c4 = (idx & 7) * 4;
                xr[p] = *(const float4*)&x[(size_t)(row0 + r) * EE + kb + c4];
            }
#pragma unroll
            for (int p = 0; p < 2; p++) {
                const int idx = tid + p * 256;
                const int r = idx >> 4, c4 = (idx & 15) * 4;
                wreg[0][p] = *(const float4*)&Wq[(size_t)(kb + r) * HDD + c4];
                wreg[1][p] = *(const float4*)&Wk[(size_t)(kb + r) * HDD + c4];
                wreg[2][p] = *(const float4*)&Wv[(size_t)(kb + r) * HDD + c4];
            }
        }
        __syncthreads();

#pragma unroll
        for (int ks = 0; ks < 4; ks++) {
            const int k0 = ks * 8;
            uint32_t a[4][4];
#pragma unroll
            for (int mt = 0; mt < 4; mt++) {
                const int r = wr * 64 + mt * 16 + gp;
                a[mt][0] = __float_as_uint(Xb[r * XS_STRIDE + k0 + qd]);
                a[mt][1] = __float_as_uint(Xb[(r + 8) * XS_STRIDE + k0 + qd]);
                a[mt][2] = __float_as_uint(Xb[r * XS_STRIDE + k0 + qd + 4]);
                a[mt][3] = __float_as_uint(Xb[(r + 8) * XS_STRIDE + k0 + qd + 4]);
            }
#pragma unroll
            for (int nt = 0; nt < 6; nt++) {
                uint32_t b[2];
                const int n = wc * 48 + nt * 8 + gp;
                b[0] = __float_as_uint(Wb[(k0 + qd) * WS3_STRIDE + n]);
                b[1] = __float_as_uint(Wb[(k0 + qd + 4) * WS3_STRIDE + n]);
#pragma unroll
                for (int mt = 0; mt < 4; mt++) mma8(acc[mt][nt], a[mt], b);
            }
        }
    }

#pragma unroll
    for (int mt = 0; mt < 4; mt++) {
#pragma unroll
        for (int nt = 0; nt < 6; nt++) {
            const int r = row0 + wr * 64 + mt * 16 + gp;
            const int col192 = wc * 48 + nt * 8 + 2 * qd;
            float* outp = (col192 < 64) ? g_q : (col192 < 128) ? g_k : g_v;
            const int c = col192 & 63;
            *(float2*)&outp[(size_t)r * HDD + c] =
                make_float2(f2tff(acc[mt][nt][0]), f2tff(acc[mt][nt][1]));
            *(float2*)&outp[(size_t)(r + 8) * HDD + c] =
                make_float2(f2tff(acc[mt][nt][2]), f2tff(acc[mt][nt][3]));
        }
    }
}

// ---------------------------------------------------------------------------
// Stage 2: split-kv causal flash attention, base-2 softmax,
// fragment-ordered K/V/Q smem (LDS.64 / LDS.128 operand feeds).
// grid (40, 8), block 256, 2 CTAs/SM.
//
// Fragment layouts:
//  Qf: [warp][ks][lane] float4 {a0,a1,a2,a3}          (8192 floats, 32KB)
//  Kf/Vf: [ks][nt][lane] float2 {b0,b1}, nt-stride 33, ks-stride 266 float2
//  Ps: row-major [128][68] (unchanged)
// ---------------------------------------------------------------------------
#define NTSTR 33                      // float2 per nt row (padded)
#define KFSTR 266                     // float2 per ks block (8*33 + 2 pad)
#define QF_FLOATS 8192                // 8 warps * 8 ks * 32 lanes * 4
#define KF_FLOATS (8 * KFSTR * 2)     // 4256
#define QS 68
#define PS_OFF (QF_FLOATS + 2 * KF_FLOATS)                    // 16704
#define ATTN_SMEM_BYTES ((PS_OFF + 128 * QS) * 4)             // 101632

__global__ __launch_bounds__(256, 2) void attn_kernel(float* __restrict__ out)
{
    extern __shared__ float sm[];
    float* Qf = sm;                       // fragment-ordered Q
    float* Kf = sm + QF_FLOATS;           // fragment-ordered K tile
    float* Vf = sm + QF_FLOATS + KF_FLOATS;
    float* Ps = sm + PS_OFF;

    const int tid  = threadIdx.x;
    const int warp = tid >> 5;
    const int lane = tid & 31;
    const int qd   = lane & 3;
    const int gp   = lane >> 2;
    const int b    = blockIdx.y;

    // map blockIdx.x -> (qt, chunk)
    int xx = blockIdx.x, qt = 0, ck = 0;
    for (qt = 0; qt < 16; qt++) {
        const int n = (qt + 4) >> 2;
        if (xx < n) { ck = xx; break; }
        xx -= n;
    }
    const int nc = (qt + 4) >> 2;
    const int j0 = ck * 8;
    const int j1 = min(ck * 8 + 8, 2 * (qt + 1));

    const int ldr  = tid >> 4;            // 0..15
    const int ldc4 = (tid & 15) * 4;      // 0,4,...,60

    // ---- Q fragment fill (once per CTA): fold SCALE*log2e, tf32-round ----
    {
        const float* qptr = g_q + ((size_t)b * TT + qt * 128) * HDD;
        const int ksq   = ldc4 >> 3;
        const int khalf = (ldc4 >> 2) & 1;
#pragma unroll
        for (int p = 0; p < 8; p++) {
            const int row = ldr + p * 16;
            float4 v = *(const float4*)&qptr[(size_t)row * HDD + ldc4];
            const int w   = row >> 4;
            const int rr  = row & 15;
            const int gpq = rr & 7;
            const int regidx = (rr >> 3) + 2 * khalf;
            float* d = &Qf[((w * 8 + ksq) * 32 + gpq * 4) * 4 + regidx];
            d[0]  = f2tff(v.x * SCALE_LOG2E);
            d[4]  = f2tff(v.y * SCALE_LOG2E);
            d[8]  = f2tff(v.z * SCALE_LOG2E);
            d[12] = f2tff(v.w * SCALE_LOG2E);
        }
    }

    const int r0  = warp * 16 + gp;
    const int rg0 = qt * 128 + r0;

    float m0 = -1e30f, m1 = -1e30f, l0 = 0.0f, l1 = 0.0f;
    float o[8][4];
#pragma unroll
    for (int nt = 0; nt < 8; nt++)
#pragma unroll
        for (int i = 0; i < 4; i++) o[nt][i] = 0.0f;

    // prefetch first K/V tile into registers
    float4 kr[4], vr[4];
    {
        const float* kp = g_k + ((size_t)b * TT + j0 * 64) * HDD;
        const float* vp = g_v + ((size_t)b * TT + j0 * 64) * HDD;
#pragma unroll
        for (int p = 0; p < 4; p++) {
            kr[p] = *(const float4*)&kp[(size_t)(ldr + p * 16) * HDD + ldc4];
            vr[p] = *(const float4*)&vp[(size_t)(ldr + p * 16) * HDD + ldc4];
        }
    }

    // per-thread constants for the fragment scatters
    const int kskA  = ldc4 >> 3;          // K: ks from hd offset
    const int halfA = (ldc4 >> 2) & 1;    // K: b0/b1 from hd offset
    const int ntV   = ldc4 >> 3;          // V: nt from hd offset
    const int gpbV  = ldc4 & 7;           // V: gp base from hd offset (0 or 4)

    for (int j64 = j0; j64 < j1; j64++) {
        __syncthreads();   // previous tile fully consumed (also orders Qf fill)
        // ---- scatter prefetched K/V into fragment order ----
#pragma unroll
        for (int p = 0; p < 4; p++) {
            const int n  = ldr + p * 16;      // kv position
            // K: value (n, ldc4+i) -> [ks=kskA][nt=n>>3][lane=(n&7)*4+i], half
            {
                float* d = &Kf[(kskA * KFSTR + (n >> 3) * NTSTR + (n & 7) * 4) * 2 + halfA];
                d[0] = kr[p].x; d[2] = kr[p].y; d[4] = kr[p].z; d[6] = kr[p].w;
            }
            // V: value (kvpos=n, hd=ldc4+i) -> [ks=n>>3][nt=ntV][lane=(gpbV+i)*4 + (n&3)], half=(n>>2)&1
            {
                float* d = &Vf[((n >> 3) * KFSTR + ntV * NTSTR + gpbV * 4 + (n & 3)) * 2 + ((n >> 2) & 1)];
                d[0] = vr[p].x; d[8] = vr[p].y; d[16] = vr[p].z; d[24] = vr[p].w;
            }
        }
        // issue next tile's loads now — latency hides under this tile's compute
        if (j64 + 1 < j1) {
            const float* kp = g_k + ((size_t)b * TT + (j64 + 1) * 64) * HDD;
            const float* vp = g_v + ((size_t)b * TT + (j64 + 1) * 64) * HDD;
#pragma unroll
            for (int p = 0; p < 4; p++) {
                kr[p] = *(const float4*)&kp[(size_t)(ldr + p * 16) * HDD + ldc4];
                vr[p] = *(const float4*)&vp[(size_t)(ldr + p * 16) * HDD + ldc4];
            }
        }
        __syncthreads();

        // ---- S'[16 x 64] = Qscaled rows @ K^T (fragment-fed mma) ----
        float s[8][4];
#pragma unroll
        for (int nt = 0; nt < 8; nt++)
#pragma unroll
            for (int i = 0; i < 4; i++) s[nt][i] = 0.0f;

#pragma unroll
        for (int ks = 0; ks < 8; ks++) {
            uint4 aq = *(const uint4*)&Qf[((warp * 8 + ks) * 32 + lane) * 4];
#pragma unroll
            for (int nt = 0; nt < 8; nt++) {
                float2 b2 = *(const float2*)&Kf[(ks * KFSTR + nt * NTSTR + lane) * 2];
                mma8(s[nt], (const uint32_t*)&aq, (const uint32_t*)&b2);
            }
        }

        // causal mask (only diagonal tiles)
        if (j64 >= 2 * qt) {
#pragma unroll
            for (int nt = 0; nt < 8; nt++) {
                const int c = j64 * 64 + nt * 8 + 2 * qd;
                if (c     > rg0)     s[nt][0] = -1e30f;
                if (c + 1 > rg0)     s[nt][1] = -1e30f;
                if (c     > rg0 + 8) s[nt][2] = -1e30f;
                if (c + 1 > rg0 + 8) s[nt][3] = -1e30f;
            }
        }

        float mx0 = -1e30f, mx1 = -1e30f;
#pragma unroll
        for (int nt = 0; nt < 8; nt++) {
            mx0 = fmaxf(mx0, fmaxf(s[nt][0], s[nt][1]));
            mx1 = fmaxf(mx1, fmaxf(s[nt][2], s[nt][3]));
        }
        mx0 = fmaxf(mx0, __shfl_xor_sync(0xffffffffu, mx0, 1));
        mx0 = fmaxf(mx0, __shfl_xor_sync(0xffffffffu, mx0, 2));
        mx1 = fmaxf(mx1, __shfl_xor_sync(0xffffffffu, mx1, 1));
        mx1 = fmaxf(mx1, __shfl_xor_sync(0xffffffffu, mx1, 2));

        const float nm0 = fmaxf(m0, mx0);
        const float nm1 = fmaxf(m1, mx1);
        const float a0 = ex2(m0 - nm0);
        const float a1 = ex2(m1 - nm1);
        m0 = nm0; m1 = nm1;

        float sum0 = 0.0f, sum1 = 0.0f;
#pragma unroll
        for (int nt = 0; nt < 8; nt++) {
            s[nt][0] = ex2(s[nt][0] - nm0);
            s[nt][1] = ex2(s[nt][1] - nm0);
            s[nt][2] = ex2(s[nt][2] - nm1);
            s[nt][3] = ex2(s[nt][3] - nm1);
            sum0 += s[nt][0] + s[nt][1];
            sum1 += s[nt][2] + s[nt][3];
        }
        sum0 += __shfl_xor_sync(0xffffffffu, sum0, 1);
        sum0 += __shfl_xor_sync(0xffffffffu, sum0, 2);
        sum1 += __shfl_xor_sync(0xffffffffu, sum1, 1);
        sum1 += __shfl_xor_sync(0xffffffffu, sum1, 2);
        l0 = l0 * a0 + sum0;
        l1 = l1 * a1 + sum1;

#pragma unroll
        for (int nt = 0; nt < 8; nt++) {
            o[nt][0] *= a0; o[nt][1] *= a0;
            o[nt][2] *= a1; o[nt][3] *= a1;
        }

        // stage P (tf32) into warp-private smem rows
#pragma unroll
        for (int nt = 0; nt < 8; nt++) {
            const int c = nt * 8 + 2 * qd;
            *(float2*)&Ps[r0 * QS + c]       = make_float2(f2tff(s[nt][0]), f2tff(s[nt][1]));
            *(float2*)&Ps[(r0 + 8) * QS + c] = make_float2(f2tff(s[nt][2]), f2tff(s[nt][3]));
        }
        __syncwarp();

        // ---- O += P[16 x 64] @ V[64 x 64] (V fragment-fed) ----
#pragma unroll
        for (int ks = 0; ks < 8; ks++) {
            const int k0 = ks * 8;
            uint32_t a[4];
            a[0] = __float_as_uint(Ps[r0 * QS + k0 + qd]);
            a[1] = __float_as_uint(Ps[(r0 + 8) * QS + k0 + qd]);
            a[2] = __float_as_uint(Ps[r0 * QS + k0 + qd + 4]);
            a[3] = __float_as_uint(Ps[(r0 + 8) * QS + k0 + qd + 4]);
#pragma unroll
            for (int nt = 0; nt < 8; nt++) {
                float2 b2 = *(const float2*)&Vf[(ks * KFSTR + nt * NTSTR + lane) * 2];
                mma8(o[nt], a, (const uint32_t*)&b2);
            }
        }
    }

    if (nc == 1) {
        const float inv0 = 1.0f / l0;
        const float inv1 = 1.0f / l1;
        float* op = out + ((size_t)b * TT + qt * 128) * HDD;
#pragma unroll
        for (int nt = 0; nt < 8; nt++) {
            const int c = nt * 8 + 2 * qd;
            *(float2*)&op[(size_t)r0 * HDD + c]       = make_float2(o[nt][0] * inv0, o[nt][1] * inv0);
            *(float2*)&op[(size_t)(r0 + 8) * HDD + c] = make_float2(o[nt][2] * inv1, o[nt][3] * inv1);
        }
    } else {
        const int pidx = (b * 16 + qt) * 4 + ck;
        float* po = g_po + (size_t)pidx * 128 * HDD;
#pragma unroll
        for (int nt = 0; nt < 8; nt++) {
            const int c = nt * 8 + 2 * qd;
            *(float2*)&po[(size_t)r0 * HDD + c]       = make_float2(o[nt][0], o[nt][1]);
            *(float2*)&po[(size_t)(r0 + 8) * HDD + c] = make_float2(o[nt][2], o[nt][3]);
        }
        if (qd == 0) {
            g_pm[pidx * 128 + r0]     = m0;
            g_pm[pidx * 128 + r0 + 8] = m1;
            g_pl[pidx * 128 + r0]     = l0;
            g_pl[pidx * 128 + r0 + 8] = l1;
        }
    }
}

// ---------------------------------------------------------------------------
// Stage 3: combine split-kv partials (base-2 domain). grid (12, 8).
// ---------------------------------------------------------------------------
__global__ __launch_bounds__(256) void combine_kernel(float* __restrict__ out)
{
    const int qt  = blockIdx.x + 4;
    const int b   = blockIdx.y;
    const int nc  = (qt + 4) >> 2;
    const int tid = threadIdx.x;
    const int r    = tid >> 1;
    const int half = (tid & 1) * 32;
    const int base = (b * 16 + qt) * 4;

    float m[4], l[4], w[4];
    float mstar = -1e30f;
#pragma unroll 4
    for (int c = 0; c < nc; c++) {
        m[c] = g_pm[(base + c) * 128 + r];
        l[c] = g_pl[(base + c) * 128 + r];
        mstar = fmaxf(mstar, m[c]);
    }
    float lstar = 0.0f;
#pragma unroll 4
    for (int c = 0; c < nc; c++) {
        float e;
        asm("ex2.approx.f32 %0, %1;" : "=f"(e) : "f"(m[c] - mstar));
        w[c] = e;
        lstar += e * l[c];
    }
    const float inv = 1.0f / lstar;
#pragma unroll 4
    for (int c = 0; c < nc; c++) w[c] *= inv;

    float* op = out + ((size_t)b * TT + qt * 128 + r) * HDD + half;
#pragma unroll
    for (int g = 0; g < 8; g++) {
        float4 acc = make_float4(0.f, 0.f, 0.f, 0.f);
#pragma unroll 4
        for (int c = 0; c < nc; c++) {
            const float4 v = *(const float4*)&g_po[(size_t)(base + c) * 128 * HDD + r * HDD + half + g * 4];
            acc.x += w[c] * v.x; acc.y += w[c] * v.y;
            acc.z += w[c] * v.z; acc.w += w[c] * v.w;
        }
        *(float4*)&op[g * 4] = acc;
    }
}

// ---------------------------------------------------------------------------
// launch
// ---------------------------------------------------------------------------
extern "C" void kernel_launch(void* const* d_in, const int* in_sizes, int n_in,
                              void* d_out, int out_size)
{
    const float* x  = (const float*)d_in[0];
    const float* Wq = (const float*)d_in[1];
    const float* Wk = (const float*)d_in[2];
    const float* Wv = (const float*)d_in[3];
    float* out = (float*)d_out;

    cudaFuncSetAttribute(qkv_kernel, cudaFuncAttributeMaxDynamicSharedMemorySize,
                         QKV_SMEM_BYTES);
    qkv_kernel<<<MM / 128, 256, QKV_SMEM_BYTES>>>(x, Wq, Wk, Wv);

    cudaFuncSetAttribute(attn_kernel, cudaFuncAttributeMaxDynamicSharedMemorySize,
                         ATTN_SMEM_BYTES);
    attn_kernel<<<dim3(40, 8), 256, ATTN_SMEM_BYTES>>>(out);

    combine_kernel<<<dim3(12, 8), 256>>>(out);
}

// round 13
// speedup vs baseline: 1.6658x; 1.0704x over previous
#include <cuda_runtime.h>
#include <cstdint>

// Problem constants
#define BB 8
#define TT 2048
#define EE 1024
#define HDD 64
#define MM (BB * TT)          // 16384 rows
// SCALE * log2(e): folded into Q so softmax runs in base-2 domain
#define SCALE_LOG2E 0.1803368801111601f

// Scratch for q,k,v projections (stored pre-rounded to tf32), 4 MB each
__device__ float g_q[MM * HDD];
__device__ float g_k[MM * HDD];
__device__ float g_v[MM * HDD];
// Split-kv partials: [b][qt][chunk] x (128 rows x 64 cols) + per-row m,l
__device__ float g_po[BB * 16 * 4 * 128 * HDD];
__device__ float g_pm[BB * 16 * 4 * 128];
__device__ float g_pl[BB * 16 * 4 * 128];

// Longest-chunk-first dispatch table: entry = qt*4 + ck, sorted by
// chunk length (8,8,...,6,6,4,4,2,2). 40 entries; block = entry*8 + b.
__constant__ uint8_t c_sched[40] = {
    // len 8 (28)
    12, 16, 20, 24, 28, 29, 32, 33, 36, 37, 40, 41, 44, 45, 46,
    48, 49, 50, 52, 53, 54, 56, 57, 58, 60, 61, 62, 63,
    // len 6 (4)
    8, 25, 42, 59,
    // len 4 (4)
    4, 21, 38, 55,
    // len 2 (4)
    0, 17, 34, 51
};

// ---------------------------------------------------------------------------
// helpers
// ---------------------------------------------------------------------------
__device__ __forceinline__ float f2tff(float x) {
    uint32_t u;
    asm("cvt.rna.tf32.f32 %0, %1;" : "=r"(u) : "f"(x));
    return __uint_as_float(u);
}

__device__ __forceinline__ float ex2(float x) {
    float r;
    asm("ex2.approx.f32 %0, %1;" : "=f"(r) : "f"(x));
    return r;
}

__device__ __forceinline__ void mma8(float* c, const uint32_t* a, const uint32_t* b) {
    asm volatile(
        "mma.sync.aligned.m16n8k8.row.col.f32.tf32.tf32.f32 "
        "{%0,%1,%2,%3}, {%4,%5,%6,%7}, {%8,%9}, {%0,%1,%2,%3};"
        : "+f"(c[0]), "+f"(c[1]), "+f"(c[2]), "+f"(c[3])
        : "r"(a[0]), "r"(a[1]), "r"(a[2]), "r"(a[3]), "r"(b[0]), "r"(b[1]));
}

// ---------------------------------------------------------------------------
// Stage 1: fused QKV projection (exact R2 config — measured ~55us clean).
// CTA tile 128 rows x 192 cols (Q|K|V heads). grid 128, block 256.
// ---------------------------------------------------------------------------
#define XS_STRIDE 36
#define WS3_STRIDE 196
#define XS_BUF (128 * XS_STRIDE)
#define WS_BUF (32 * WS3_STRIDE)
#define QKV_SMEM_BYTES ((2 * XS_BUF + 2 * WS_BUF) * 4)   // 87040

__global__ __launch_bounds__(256) void qkv_kernel(
    const float* __restrict__ x,
    const float* __restrict__ Wq,
    const float* __restrict__ Wk,
    const float* __restrict__ Wv)
{
    extern __shared__ float sm[];
    float* Xs = sm;
    float* Ws = sm + 2 * XS_BUF;

    const int tid  = threadIdx.x;
    const int warp = tid >> 5;
    const int lane = tid & 31;
    const int qd   = lane & 3;
    const int gp   = lane >> 2;
    const int wr   = warp & 1;
    const int wc   = warp >> 1;

    const int row0 = blockIdx.x * 128;

    float acc[4][6][4];
#pragma unroll
    for (int mt = 0; mt < 4; mt++)
#pragma unroll
        for (int nt = 0; nt < 6; nt++)
#pragma unroll
            for (int i = 0; i < 4; i++) acc[mt][nt][i] = 0.0f;

    float4 xr[4];
    float4 wreg[3][2];

#pragma unroll
    for (int p = 0; p < 4; p++) {
        const int idx = tid + p * 256;
        const int r = idx >> 3, c4 = (idx & 7) * 4;
        xr[p] = *(const float4*)&x[(size_t)(row0 + r) * EE + c4];
    }
#pragma unroll
    for (int p = 0; p < 2; p++) {
        const int idx = tid + p * 256;
        const int r = idx >> 4, c4 = (idx & 15) * 4;
        wreg[0][p] = *(const float4*)&Wq[(size_t)r * HDD + c4];
        wreg[1][p] = *(const float4*)&Wk[(size_t)r * HDD + c4];
        wreg[2][p] = *(const float4*)&Wv[(size_t)r * HDD + c4];
    }

    for (int kbi = 0; kbi < 32; kbi++) {
        float* Xb = Xs + (kbi & 1) * XS_BUF;
        float* Wb = Ws + (kbi & 1) * WS_BUF;

#pragma unroll
        for (int p = 0; p < 4; p++) {
            const int idx = tid + p * 256;
            const int r = idx >> 3, c4 = (idx & 7) * 4;
            float* d = &Xb[r * XS_STRIDE + c4];
            d[0] = f2tff(xr[p].x); d[1] = f2tff(xr[p].y);
            d[2] = f2tff(xr[p].z); d[3] = f2tff(xr[p].w);
        }
#pragma unroll
        for (int w = 0; w < 3; w++)
#pragma unroll
            for (int p = 0; p < 2; p++) {
                const int idx = tid + p * 256;
                const int r = idx >> 4, c4 = (idx & 15) * 4;
                float* d = &Wb[r * WS3_STRIDE + w * 64 + c4];
                d[0] = f2tff(wreg[w][p].x); d[1] = f2tff(wreg[w][p].y);
                d[2] = f2tff(wreg[w][p].z); d[3] = f2tff(wreg[w][p].w);
            }

        if (kbi < 31) {
            const int kb = (kbi + 1) * 32;
#pragma unroll
            for (int p = 0; p < 4; p++) {
                const int idx = tid + p * 256;
                const int r = idx >> 3, c4 = (idx & 7) * 4;
                xr[p] = *(const float4*)&x[(size_t)(row0 + r) * EE + kb + c4];
            }
#pragma unroll
            for (int p = 0; p < 2; p++) {
                const int idx = tid + p * 256;
                const int r = idx >> 4, c4 = (idx & 15) * 4;
                wreg[0][p] = *(const float4*)&Wq[(size_t)(kb + r) * HDD + c4];
                wreg[1][p] = *(const float4*)&Wk[(size_t)(kb + r) * HDD + c4];
                wreg[2][p] = *(const float4*)&Wv[(size_t)(kb + r) * HDD + c4];
            }
        }
        __syncthreads();

#pragma unroll
        for (int ks = 0; ks < 4; ks++) {
            const int k0 = ks * 8;
            uint32_t a[4][4];
#pragma unroll
            for (int mt = 0; mt < 4; mt++) {
                const int r = wr * 64 + mt * 16 + gp;
                a[mt][0] = __float_as_uint(Xb[r * XS_STRIDE + k0 + qd]);
                a[mt][1] = __float_as_uint(Xb[(r + 8) * XS_STRIDE + k0 + qd]);
                a[mt][2] = __float_as_uint(Xb[r * XS_STRIDE + k0 + qd + 4]);
                a[mt][3] = __float_as_uint(Xb[(r + 8) * XS_STRIDE + k0 + qd + 4]);
            }
#pragma unroll
            for (int nt = 0; nt < 6; nt++) {
                uint32_t b[2];
                const int n = wc * 48 + nt * 8 + gp;
                b[0] = __float_as_uint(Wb[(k0 + qd) * WS3_STRIDE + n]);
                b[1] = __float_as_uint(Wb[(k0 + qd + 4) * WS3_STRIDE + n]);
#pragma unroll
                for (int mt = 0; mt < 4; mt++) mma8(acc[mt][nt], a[mt], b);
            }
        }
    }

#pragma unroll
    for (int mt = 0; mt < 4; mt++) {
#pragma unroll
        for (int nt = 0; nt < 6; nt++) {
            const int r = row0 + wr * 64 + mt * 16 + gp;
            const int col192 = wc * 48 + nt * 8 + 2 * qd;
            float* outp = (col192 < 64) ? g_q : (col192 < 128) ? g_k : g_v;
            const int c = col192 & 63;
            *(float2*)&outp[(size_t)r * HDD + c] =
                make_float2(f2tff(acc[mt][nt][0]), f2tff(acc[mt][nt][1]));
            *(float2*)&outp[(size_t)(r + 8) * HDD + c] =
                make_float2(f2tff(acc[mt][nt][2]), f2tff(acc[mt][nt][3]));
        }
    }
}

// ---------------------------------------------------------------------------
// Stage 2: split-kv causal flash attention, base-2 softmax,
// fragment-ordered K/V/Q smem, LONGEST-CHUNK-FIRST 1-D dispatch.
// grid 320 (1-D), block 256, 2 CTAs/SM.
// ---------------------------------------------------------------------------
#define NTSTR 33
#define KFSTR 266
#define QF_FLOATS 8192
#define KF_FLOATS (8 * KFSTR * 2)
#define QS 68
#define PS_OFF (QF_FLOATS + 2 * KF_FLOATS)
#define ATTN_SMEM_BYTES ((PS_OFF + 128 * QS) * 4)             // 101632

__global__ __launch_bounds__(256, 2) void attn_kernel(float* __restrict__ out)
{
    extern __shared__ float sm[];
    float* Qf = sm;
    float* Kf = sm + QF_FLOATS;
    float* Vf = sm + QF_FLOATS + KF_FLOATS;
    float* Ps = sm + PS_OFF;

    const int tid  = threadIdx.x;
    const int warp = tid >> 5;
    const int lane = tid & 31;
    const int qd   = lane & 3;
    const int gp   = lane >> 2;

    // longest-first dispatch: block = entry*8 + b
    const int b    = blockIdx.x & 7;
    const int code = c_sched[blockIdx.x >> 3];
    const int qt   = code >> 2;
    const int ck   = code & 3;

    const int nc = (qt + 4) >> 2;
    const int j0 = ck * 8;
    const int j1 = min(ck * 8 + 8, 2 * (qt + 1));

    const int ldr  = tid >> 4;            // 0..15
    const int ldc4 = (tid & 15) * 4;      // 0,4,...,60

    // ---- Q fragment fill (once per CTA): fold SCALE*log2e, tf32-round ----
    {
        const float* qptr = g_q + ((size_t)b * TT + qt * 128) * HDD;
        const int ksq   = ldc4 >> 3;
        const int khalf = (ldc4 >> 2) & 1;
#pragma unroll
        for (int p = 0; p < 8; p++) {
            const int row = ldr + p * 16;
            float4 v = *(const float4*)&qptr[(size_t)row * HDD + ldc4];
            const int w   = row >> 4;
            const int rr  = row & 15;
            const int gpq = rr & 7;
            const int regidx = (rr >> 3) + 2 * khalf;
            float* d = &Qf[((w * 8 + ksq) * 32 + gpq * 4) * 4 + regidx];
            d[0]  = f2tff(v.x * SCALE_LOG2E);
            d[4]  = f2tff(v.y * SCALE_LOG2E);
            d[8]  = f2tff(v.z * SCALE_LOG2E);
            d[12] = f2tff(v.w * SCALE_LOG2E);
        }
    }

    const int r0  = warp * 16 + gp;
    const int rg0 = qt * 128 + r0;

    float m0 = -1e30f, m1 = -1e30f, l0 = 0.0f, l1 = 0.0f;
    float o[8][4];
#pragma unroll
    for (int nt = 0; nt < 8; nt++)
#pragma unroll
        for (int i = 0; i < 4; i++) o[nt][i] = 0.0f;

    // prefetch first K/V tile into registers
    float4 kr[4], vr[4];
    {
        const float* kp = g_k + ((size_t)b * TT + j0 * 64) * HDD;
        const float* vp = g_v + ((size_t)b * TT + j0 * 64) * HDD;
#pragma unroll
        for (int p = 0; p < 4; p++) {
            kr[p] = *(const float4*)&kp[(size_t)(ldr + p * 16) * HDD + ldc4];
            vr[p] = *(const float4*)&vp[(size_t)(ldr + p * 16) * HDD + ldc4];
        }
    }

    const int kskA  = ldc4 >> 3;
    const int halfA = (ldc4 >> 2) & 1;
    const int ntV   = ldc4 >> 3;
    const int gpbV  = ldc4 & 7;

    for (int j64 = j0; j64 < j1; j64++) {
        __syncthreads();
#pragma unroll
        for (int p = 0; p < 4; p++) {
            const int n  = ldr + p * 16;
            {
                float* d = &Kf[(kskA * KFSTR + (n >> 3) * NTSTR + (n & 7) * 4) * 2 + halfA];
                d[0] = kr[p].x; d[2] = kr[p].y; d[4] = kr[p].z; d[6] = kr[p].w;
            }
            {
                float* d = &Vf[((n >> 3) * KFSTR + ntV * NTSTR + gpbV * 4 + (n & 3)) * 2 + ((n >> 2) & 1)];
                d[0] = vr[p].x; d[8] = vr[p].y; d[16] = vr[p].z; d[24] = vr[p].w;
            }
        }
        if (j64 + 1 < j1) {
            const float* kp = g_k + ((size_t)b * TT + (j64 + 1) * 64) * HDD;
            const float* vp = g_v + ((size_t)b * TT + (j64 + 1) * 64) * HDD;
#pragma unroll
            for (int p = 0; p < 4; p++) {
                kr[p] = *(const float4*)&kp[(size_t)(ldr + p * 16) * HDD + ldc4];
                vr[p] = *(const float4*)&vp[(size_t)(ldr + p * 16) * HDD + ldc4];
            }
        }
        __syncthreads();

        float s[8][4];
#pragma unroll
        for (int nt = 0; nt < 8; nt++)
#pragma unroll
            for (int i = 0; i < 4; i++) s[nt][i] = 0.0f;

#pragma unroll
        for (int ks = 0; ks < 8; ks++) {
            uint4 aq = *(const uint4*)&Qf[((warp * 8 + ks) * 32 + lane) * 4];
#pragma unroll
            for (int nt = 0; nt < 8; nt++) {
                float2 b2 = *(const float2*)&Kf[(ks * KFSTR + nt * NTSTR + lane) * 2];
                mma8(s[nt], (const uint32_t*)&aq, (const uint32_t*)&b2);
            }
        }

        if (j64 >= 2 * qt) {
#pragma unroll
            for (int nt = 0; nt < 8; nt++) {
                const int c = j64 * 64 + nt * 8 + 2 * qd;
                if (c     > rg0)     s[nt][0] = -1e30f;
                if (c + 1 > rg0)     s[nt][1] = -1e30f;
                if (c     > rg0 + 8) s[nt][2] = -1e30f;
                if (c + 1 > rg0 + 8) s[nt][3] = -1e30f;
            }
        }

        float mx0 = -1e30f, mx1 = -1e30f;
#pragma unroll
        for (int nt = 0; nt < 8; nt++) {
            mx0 = fmaxf(mx0, fmaxf(s[nt][0], s[nt][1]));
            mx1 = fmaxf(mx1, fmaxf(s[nt][2], s[nt][3]));
        }
        mx0 = fmaxf(mx0, __shfl_xor_sync(0xffffffffu, mx0, 1));
        mx0 = fmaxf(mx0, __shfl_xor_sync(0xffffffffu, mx0, 2));
        mx1 = fmaxf(mx1, __shfl_xor_sync(0xffffffffu, mx1, 1));
        mx1 = fmaxf(mx1, __shfl_xor_sync(0xffffffffu, mx1, 2));

        const float nm0 = fmaxf(m0, mx0);
        const float nm1 = fmaxf(m1, mx1);
        const float a0 = ex2(m0 - nm0);
        const float a1 = ex2(m1 - nm1);
        m0 = nm0; m1 = nm1;

        float sum0 = 0.0f, sum1 = 0.0f;
#pragma unroll
        for (int nt = 0; nt < 8; nt++) {
            s[nt][0] = ex2(s[nt][0] - nm0);
            s[nt][1] = ex2(s[nt][1] - nm0);
            s[nt][2] = ex2(s[nt][2] - nm1);
            s[nt][3] = ex2(s[nt][3] - nm1);
            sum0 += s[nt][0] + s[nt][1];
            sum1 += s[nt][2] + s[nt][3];
        }
        sum0 += __shfl_xor_sync(0xffffffffu, sum0, 1);
        sum0 += __shfl_xor_sync(0xffffffffu, sum0, 2);
        sum1 += __shfl_xor_sync(0xffffffffu, sum1, 1);
        sum1 += __shfl_xor_sync(0xffffffffu, sum1, 2);
        l0 = l0 * a0 + sum0;
        l1 = l1 * a1 + sum1;

#pragma unroll
        for (int nt = 0; nt < 8; nt++) {
            o[nt][0] *= a0; o[nt][1] *= a0;
            o[nt][2] *= a1; o[nt][3] *= a1;
        }

#pragma unroll
        for (int nt = 0; nt < 8; nt++) {
            const int c = nt * 8 + 2 * qd;
            *(float2*)&Ps[r0 * QS + c]       = make_float2(f2tff(s[nt][0]), f2tff(s[nt][1]));
            *(float2*)&Ps[(r0 + 8) * QS + c] = make_float2(f2tff(s[nt][2]), f2tff(s[nt][3]));
        }
        __syncwarp();

#pragma unroll
        for (int ks = 0; ks < 8; ks++) {
            const int k0 = ks * 8;
            uint32_t a[4];
            a[0] = __float_as_uint(Ps[r0 * QS + k0 + qd]);
            a[1] = __float_as_uint(Ps[(r0 + 8) * QS + k0 + qd]);
            a[2] = __float_as_uint(Ps[r0 * QS + k0 + qd + 4]);
            a[3] = __float_as_uint(Ps[(r0 + 8) * QS + k0 + qd + 4]);
#pragma unroll
            for (int nt = 0; nt < 8; nt++) {
                float2 b2 = *(const float2*)&Vf[(ks * KFSTR + nt * NTSTR + lane) * 2];
                mma8(o[nt], a, (const uint32_t*)&b2);
            }
        }
    }

    if (nc == 1) {
        const float inv0 = 1.0f / l0;
        const float inv1 = 1.0f / l1;
        float* op = out + ((size_t)b * TT + qt * 128) * HDD;
#pragma unroll
        for (int nt = 0; nt < 8; nt++) {
            const int c = nt * 8 + 2 * qd;
            *(float2*)&op[(size_t)r0 * HDD + c]       = make_float2(o[nt][0] * inv0, o[nt][1] * inv0);
            *(float2*)&op[(size_t)(r0 + 8) * HDD + c] = make_float2(o[nt][2] * inv1, o[nt][3] * inv1);
        }
    } else {
        const int pidx = (b * 16 + qt) * 4 + ck;
        float* po = g_po + (size_t)pidx * 128 * HDD;
#pragma unroll
        for (int nt = 0; nt < 8; nt++) {
            const int c = nt * 8 + 2 * qd;
            *(float2*)&po[(size_t)r0 * HDD + c]       = make_float2(o[nt][0], o[nt][1]);
            *(float2*)&po[(size_t)(r0 + 8) * HDD + c] = make_float2(o[nt][2], o[nt][3]);
        }
        if (qd == 0) {
            g_pm[pidx * 128 + r0]     = m0;
            g_pm[pidx * 128 + r0 + 8] = m1;
            g_pl[pidx * 128 + r0]     = l0;
            g_pl[pidx * 128 + r0 + 8] = l1;
        }
    }
}

// ---------------------------------------------------------------------------
// Stage 3: combine split-kv partials (base-2 domain). grid (12, 8).
// ---------------------------------------------------------------------------
__global__ __launch_bounds__(256) void combine_kernel(float* __restrict__ out)
{
    const int qt  = blockIdx.x + 4;
    const int b   = blockIdx.y;
    const int nc  = (qt + 4) >> 2;
    const int tid = threadIdx.x;
    const int r    = tid >> 1;
    const int half = (tid & 1) * 32;
    const int base = (b * 16 + qt) * 4;

    float m[4], l[4], w[4];
    float mstar = -1e30f;
#pragma unroll 4
    for (int c = 0; c < nc; c++) {
        m[c] = g_pm[(base + c) * 128 + r];
        l[c] = g_pl[(base + c) * 128 + r];
        mstar = fmaxf(mstar, m[c]);
    }
    float lstar = 0.0f;
#pragma unroll 4
    for (int c = 0; c < nc; c++) {
        float e;
        asm("ex2.approx.f32 %0, %1;" : "=f"(e) : "f"(m[c] - mstar));
        w[c] = e;
        lstar += e * l[c];
    }
    const float inv = 1.0f / lstar;
#pragma unroll 4
    for (int c = 0; c < nc; c++) w[c] *= inv;

    float* op = out + ((size_t)b * TT + qt * 128 + r) * HDD + half;
#pragma unroll
    for (int g = 0; g < 8; g++) {
        float4 acc = make_float4(0.f, 0.f, 0.f, 0.f);
#pragma unroll 4
        for (int c = 0; c < nc; c++) {
            const float4 v = *(const float4*)&g_po[(size_t)(base + c) * 128 * HDD + r * HDD + half + g * 4];
            acc.x += w[c] * v.x; acc.y += w[c] * v.y;
            acc.z += w[c] * v.z; acc.w += w[c] * v.w;
        }
        *(float4*)&op[g * 4] = acc;
    }
}

// ---------------------------------------------------------------------------
// launch
// ---------------------------------------------------------------------------
extern "C" void kernel_launch(void* const* d_in, const int* in_sizes, int n_in,
                              void* d_out, int out_size)
{
    const float* x  = (const float*)d_in[0];
    const float* Wq = (const float*)d_in[1];
    const float* Wk = (const float*)d_in[2];
    const float* Wv = (const float*)d_in[3];
    float* out = (float*)d_out;

    cudaFuncSetAttribute(qkv_kernel, cudaFuncAttributeMaxDynamicSharedMemorySize,
                         QKV_SMEM_BYTES);
    qkv_kernel<<<MM / 128, 256, QKV_SMEM_BYTES>>>(x, Wq, Wk, Wv);

    cudaFuncSetAttribute(attn_kernel, cudaFuncAttributeMaxDynamicSharedMemorySize,
                         ATTN_SMEM_BYTES);
    attn_kernel<<<320, 256, ATTN_SMEM_BYTES>>>(out);

    combine_kernel<<<dim3(12, 8), 256>>>(out);
}

// round 15
// speedup vs baseline: 1.7336x; 1.0407x over previous
#include <cuda_runtime.h>
#include <cstdint>

// Problem constants
#define BB 8
#define TT 2048
#define EE 1024
#define HDD 64
#define MM (BB * TT)          // 16384 rows
// SCALE * log2(e): folded into Q so softmax runs in base-2 domain
#define SCALE_LOG2E 0.1803368801111601f

// Scratch for q,k,v projections (stored pre-rounded to tf32), 4 MB each
__device__ float g_q[MM * HDD];
__device__ float g_k[MM * HDD];
__device__ float g_v[MM * HDD];
// W pre-packed into per-chunk B-fragment smem image (tf32-rounded):
// [chunk 32][ks 4][nt 24][33 float2]  -> 6336 floats per chunk
#define WF_CHUNK 6336
__device__ float g_wf[32 * WF_CHUNK];
// Split-kv partials: [b][qt][chunk] x (128 rows x 64 cols) + per-row m,l
__device__ float g_po[BB * 16 * 4 * 128 * HDD];
__device__ float g_pm[BB * 16 * 4 * 128];
__device__ float g_pl[BB * 16 * 4 * 128];

// Longest-chunk-first dispatch table for attn (entry = qt*4 + ck).
__constant__ uint8_t c_sched[40] = {
    12, 16, 20, 24, 28, 29, 32, 33, 36, 37, 40, 41, 44, 45, 46,
    48, 49, 50, 52, 53, 54, 56, 57, 58, 60, 61, 62, 63,
    8, 25, 42, 59,
    4, 21, 38, 55,
    0, 17, 34, 51
};

// ---------------------------------------------------------------------------
// helpers
// ---------------------------------------------------------------------------
__device__ __forceinline__ float f2tff(float x) {
    uint32_t u;
    asm("cvt.rna.tf32.f32 %0, %1;" : "=r"(u) : "f"(x));
    return __uint_as_float(u);
}

__device__ __forceinline__ float ex2(float x) {
    float r;
    asm("ex2.approx.f32 %0, %1;" : "=f"(r) : "f"(x));
    return r;
}

__device__ __forceinline__ void mma8(float* c, const uint32_t* a, const uint32_t* b) {
    asm volatile(
        "mma.sync.aligned.m16n8k8.row.col.f32.tf32.tf32.f32 "
        "{%0,%1,%2,%3}, {%4,%5,%6,%7}, {%8,%9}, {%0,%1,%2,%3};"
        : "+f"(c[0]), "+f"(c[1]), "+f"(c[2]), "+f"(c[3])
        : "r"(a[0]), "r"(a[1]), "r"(a[2]), "r"(a[3]), "r"(b[0]), "r"(b[1]));
}

// ---------------------------------------------------------------------------
// Stage 0: pre-pack W (tf32) into per-chunk B-fragment layout.
// 196608 elements, grid 768 x 256.
// ---------------------------------------------------------------------------
__global__ void wf_kernel(const float* __restrict__ Wq,
                          const float* __restrict__ Wk,
                          const float* __restrict__ Wv)
{
    const int idx = blockIdx.x * 256 + threadIdx.x;      // 0..196607
    const int h   = idx >> 16;                            // head 0..2
    const int rem = idx & 65535;                          // kk*64 + c
    const int kk  = rem >> 6;                             // k row 0..1023
    const int c   = rem & 63;                             // col 0..63
    const float* W = (h == 0) ? Wq : (h == 1) ? Wk : Wv;
    const float v = f2tff(W[rem]);
    const int kbi  = kk >> 5;
    const int r    = kk & 31;
    const int ks   = r >> 3;
    const int qd   = r & 3;
    const int half = (r >> 2) & 1;
    const int nt   = h * 8 + (c >> 3);
    const int gp   = c & 7;
    g_wf[kbi * WF_CHUNK + (ks * 792 + nt * 33 + gp * 4 + qd) * 2 + half] = v;
}

// ---------------------------------------------------------------------------
// Stage 1: fused QKV projection, fragment-ordered smem operands.
// CTA tile 128 rows x 192 cols. grid 128, block 256.
//  Xf: [mtile 8][ks 4] blocks of 132 floats (128 data + 4 pad): A via LDS.128
//  Wf: per-chunk image copied from g_wf: B via LDS.64
// ---------------------------------------------------------------------------
#define XF_BLK 132
#define XF_BUF (8 * 4 * XF_BLK)         // 4224 floats
#define WF_BUF WF_CHUNK                 // 6336 floats
#define QKV_SMEM_BYTES ((2 * XF_BUF + 2 * WF_BUF) * 4)   // 84480

__global__ __launch_bounds__(256) void qkv_kernel(const float* __restrict__ x)
{
    extern __shared__ float sm[];
    float* Xs = sm;                      // [2][4224]
    float* Ws = sm + 2 * XF_BUF;         // [2][6336]

    const int tid  = threadIdx.x;
    const int warp = tid >> 5;
    const int lane = tid & 31;
    const int qd   = lane & 3;
    const int gp   = lane >> 2;
    const int wr   = warp & 1;           // row half -> mtiles wr*4..wr*4+3
    const int wc   = warp >> 1;          // col block (0..3) -> nt wc*6..wc*6+5

    const int row0 = blockIdx.x * 128;

    float acc[4][6][4];
#pragma unroll
    for (int mt = 0; mt < 4; mt++)
#pragma unroll
        for (int nt = 0; nt < 6; nt++)
#pragma unroll
            for (int i = 0; i < 4; i++) acc[mt][nt][i] = 0.0f;

    // per-thread X fill constants
    // idx = tid + p*256 -> r = idx>>3, c4 = (idx&7)*4
    // store base = (mtile*4+ks)*132 + gpq*16 + regbase + 2*khalf; d[0],d[4],d[8],d[12]
    float4 xr[4];
    float4 wf4[7];
    const float4* gwf4 = (const float4*)g_wf;

    // prefetch chunk 0
#pragma unroll
    for (int p = 0; p < 4; p++) {
        const int idx = tid + p * 256;
        xr[p] = *(const float4*)&x[(size_t)(row0 + (idx >> 3)) * EE + (idx & 7) * 4];
    }
#pragma unroll
    for (int p = 0; p < 7; p++) {
        const int idx = tid + p * 256;
        if (idx < WF_CHUNK / 4) wf4[p] = gwf4[idx];
    }

    for (int kbi = 0; kbi < 32; kbi++) {
        float* Xb = Xs + (kbi & 1) * XF_BUF;
        float* Wb = Ws + (kbi & 1) * WF_BUF;

        // ---- store prefetched X into A-fragment order (tf32) ----
#pragma unroll
        for (int p = 0; p < 4; p++) {
            const int idx = tid + p * 256;
            const int r  = idx >> 3;
            const int c4 = (idx & 7) * 4;
            const int mtile   = r >> 4;
            const int rr      = r & 15;
            const int gpq     = rr & 7;
            const int regbase = rr >> 3;
            const int ks      = c4 >> 3;
            const int khalf   = (c4 >> 2) & 1;
            float* d = &Xb[(mtile * 4 + ks) * XF_BLK + gpq * 16 + regbase + 2 * khalf];
            d[0]  = f2tff(xr[p].x);
            d[4]  = f2tff(xr[p].y);
            d[8]  = f2tff(xr[p].z);
            d[12] = f2tff(xr[p].w);
        }
        // ---- store prefetched W image (already fragment-ordered + tf32) ----
        {
            float4* wdst = (float4*)Wb;
#pragma unroll
            for (int p = 0; p < 7; p++) {
                const int idx = tid + p * 256;
                if (idx < WF_CHUNK / 4) wdst[idx] = wf4[p];
            }
        }

        // ---- prefetch next chunk ----
        if (kbi < 31) {
            const int kb = (kbi + 1) * 32;
#pragma unroll
            for (int p = 0; p < 4; p++) {
                const int idx = tid + p * 256;
                xr[p] = *(const float4*)&x[(size_t)(row0 + (idx >> 3)) * EE + kb + (idx & 7) * 4];
            }
            const float4* src = gwf4 + (size_t)(kbi + 1) * (WF_CHUNK / 4);
#pragma unroll
            for (int p = 0; p < 7; p++) {
                const int idx = tid + p * 256;
                if (idx < WF_CHUNK / 4) wf4[p] = src[idx];
            }
        }
        __syncthreads();   // single barrier per chunk (double-buffered smem)

        // ---- compute: fragment-fed mma ----
#pragma unroll
        for (int ks = 0; ks < 4; ks++) {
            uint4 aq[4];
#pragma unroll
            for (int mt = 0; mt < 4; mt++)
                aq[mt] = *(const uint4*)&Xb[((wr * 4 + mt) * 4 + ks) * XF_BLK + lane * 4];
#pragma unroll
            for (int j = 0; j < 6; j++) {
                float2 b2 = *(const float2*)&Wb[(ks * 792 + (wc * 6 + j) * 33 + lane) * 2];
#pragma unroll
                for (int mt = 0; mt < 4; mt++)
                    mma8(acc[mt][j], (const uint32_t*)&aq[mt], (const uint32_t*)&b2);
            }
        }
    }

    // epilogue: route each 8-col block to q/k/v head, pre-round to tf32
#pragma unroll
    for (int mt = 0; mt < 4; mt++) {
#pragma unroll
        for (int nt = 0; nt < 6; nt++) {
            const int r = row0 + wr * 64 + mt * 16 + gp;
            const int col192 = wc * 48 + nt * 8 + 2 * qd;
            float* outp = (col192 < 64) ? g_q : (col192 < 128) ? g_k : g_v;
            const int c = col192 & 63;
            *(float2*)&outp[(size_t)r * HDD + c] =
                make_float2(f2tff(acc[mt][nt][0]), f2tff(acc[mt][nt][1]));
            *(float2*)&outp[(size_t)(r + 8) * HDD + c] =
                make_float2(f2tff(acc[mt][nt][2]), f2tff(acc[mt][nt][3]));
        }
    }
}

// ---------------------------------------------------------------------------
// Stage 2: split-kv causal flash attention (unchanged from R13 best).
// ---------------------------------------------------------------------------
#define NTSTR 33
#define KFSTR 266
#define QF_FLOATS 8192
#define KF_FLOATS (8 * KFSTR * 2)
#define QS 68
#define PS_OFF (QF_FLOATS + 2 * KF_FLOATS)
#define ATTN_SMEM_BYTES ((PS_OFF + 128 * QS) * 4)             // 101632

__global__ __launch_bounds__(256, 2) void attn_kernel(float* __restrict__ out)
{
    extern __shared__ float sm[];
    float* Qf = sm;
    float* Kf = sm + QF_FLOATS;
    float* Vf = sm + QF_FLOATS + KF_FLOATS;
    float* Ps = sm + PS_OFF;

    const int tid  = threadIdx.x;
    const int warp = tid >> 5;
    const int lane = tid & 31;
    const int qd   = lane & 3;
    const int gp   = lane >> 2;

    const int b    = blockIdx.x & 7;
    const int code = c_sched[blockIdx.x >> 3];
    const int qt   = code >> 2;
    const int ck   = code & 3;

    const int nc = (qt + 4) >> 2;
    const int j0 = ck * 8;
    const int j1 = min(ck * 8 + 8, 2 * (qt + 1));

    const int ldr  = tid >> 4;
    const int ldc4 = (tid & 15) * 4;

    {
        const float* qptr = g_q + ((size_t)b * TT + qt * 128) * HDD;
        const int ksq   = ldc4 >> 3;
        const int khalf = (ldc4 >> 2) & 1;
#pragma unroll
        for (int p = 0; p < 8; p++) {
            const int row = ldr + p * 16;
            float4 v = *(const float4*)&qptr[(size_t)row * HDD + ldc4];
            const int w   = row >> 4;
            const int rr  = row & 15;
            const int gpq = rr & 7;
            const int regidx = (rr >> 3) + 2 * khalf;
            float* d = &Qf[((w * 8 + ksq) * 32 + gpq * 4) * 4 + regidx];
            d[0]  = f2tff(v.x * SCALE_LOG2E);
            d[4]  = f2tff(v.y * SCALE_LOG2E);
            d[8]  = f2tff(v.z * SCALE_LOG2E);
            d[12] = f2tff(v.w * SCALE_LOG2E);
        }
    }

    const int r0  = warp * 16 + gp;
    const int rg0 = qt * 128 + r0;

    float m0 = -1e30f, m1 = -1e30f, l0 = 0.0f, l1 = 0.0f;
    float o[8][4];
#pragma unroll
    for (int nt = 0; nt < 8; nt++)
#pragma unroll
        for (int i = 0; i < 4; i++) o[nt][i] = 0.0f;

    float4 kr[4], vr[4];
    {
        const float* kp = g_k + ((size_t)b * TT + j0 * 64) * HDD;
        const float* vp = g_v + ((size_t)b * TT + j0 * 64) * HDD;
#pragma unroll
        for (int p = 0; p < 4; p++) {
            kr[p] = *(const float4*)&kp[(size_t)(ldr + p * 16) * HDD + ldc4];
            vr[p] = *(const float4*)&vp[(size_t)(ldr + p * 16) * HDD + ldc4];
        }
    }

    const int kskA  = ldc4 >> 3;
    const int halfA = (ldc4 >> 2) & 1;
    const int ntV   = ldc4 >> 3;
    const int gpbV  = ldc4 & 7;

    for (int j64 = j0; j64 < j1; j64++) {
        __syncthreads();
#pragma unroll
        for (int p = 0; p < 4; p++) {
            const int n  = ldr + p * 16;
            {
                float* d = &Kf[(kskA * KFSTR + (n >> 3) * NTSTR + (n & 7) * 4) * 2 + halfA];
                d[0] = kr[p].x; d[2] = kr[p].y; d[4] = kr[p].z; d[6] = kr[p].w;
            }
            {
                float* d = &Vf[((n >> 3) * KFSTR + ntV * NTSTR + gpbV * 4 + (n & 3)) * 2 + ((n >> 2) & 1)];
                d[0] = vr[p].x; d[8] = vr[p].y; d[16] = vr[p].z; d[24] = vr[p].w;
            }
        }
        if (j64 + 1 < j1) {
            const float* kp = g_k + ((size_t)b * TT + (j64 + 1) * 64) * HDD;
            const float* vp = g_v + ((size_t)b * TT + (j64 + 1) * 64) * HDD;
#pragma unroll
            for (int p = 0; p < 4; p++) {
                kr[p] = *(const float4*)&kp[(size_t)(ldr + p * 16) * HDD + ldc4];
                vr[p] = *(const float4*)&vp[(size_t)(ldr + p * 16) * HDD + ldc4];
            }
        }
        __syncthreads();

        float s[8][4];
#pragma unroll
        for (int nt = 0; nt < 8; nt++)
#pragma unroll
            for (int i = 0; i < 4; i++) s[nt][i] = 0.0f;

#pragma unroll
        for (int ks = 0; ks < 8; ks++) {
            uint4 aq = *(const uint4*)&Qf[((warp * 8 + ks) * 32 + lane) * 4];
#pragma unroll
            for (int nt = 0; nt < 8; nt++) {
                float2 b2 = *(const float2*)&Kf[(ks * KFSTR + nt * NTSTR + lane) * 2];
                mma8(s[nt], (const uint32_t*)&aq, (const uint32_t*)&b2);
            }
        }

        if (j64 >= 2 * qt) {
#pragma unroll
            for (int nt = 0; nt < 8; nt++) {
                const int c = j64 * 64 + nt * 8 + 2 * qd;
                if (c     > rg0)     s[nt][0] = -1e30f;
                if (c + 1 > rg0)     s[nt][1] = -1e30f;
                if (c     > rg0 + 8) s[nt][2] = -1e30f;
                if (c + 1 > rg0 + 8) s[nt][3] = -1e30f;
            }
        }

        float mx0 = -1e30f, mx1 = -1e30f;
#pragma unroll
        for (int nt = 0; nt < 8; nt++) {
            mx0 = fmaxf(mx0, fmaxf(s[nt][0], s[nt][1]));
            mx1 = fmaxf(mx1, fmaxf(s[nt][2], s[nt][3]));
        }
        mx0 = fmaxf(mx0, __shfl_xor_sync(0xffffffffu, mx0, 1));
        mx0 = fmaxf(mx0, __shfl_xor_sync(0xffffffffu, mx0, 2));
        mx1 = fmaxf(mx1, __shfl_xor_sync(0xffffffffu, mx1, 1));
        mx1 = fmaxf(mx1, __shfl_xor_sync(0xffffffffu, mx1, 2));

        const float nm0 = fmaxf(m0, mx0);
        const float nm1 = fmaxf(m1, mx1);
        const float a0 = ex2(m0 - nm0);
        const float a1 = ex2(m1 - nm1);
        m0 = nm0; m1 = nm1;

        float sum0 = 0.0f, sum1 = 0.0f;
#pragma unroll
        for (int nt = 0; nt < 8; nt++) {
            s[nt][0] = ex2(s[nt][0] - nm0);
            s[nt][1] = ex2(s[nt][1] - nm0);
            s[nt][2] = ex2(s[nt][2] - nm1);
            s[nt][3] = ex2(s[nt][3] - nm1);
            sum0 += s[nt][0] + s[nt][1];
            sum1 += s[nt][2] + s[nt][3];
        }
        sum0 += __shfl_xor_sync(0xffffffffu, sum0, 1);
        sum0 += __shfl_xor_sync(0xffffffffu, sum0, 2);
        sum1 += __shfl_xor_sync(0xffffffffu, sum1, 1);
        sum1 += __shfl_xor_sync(0xffffffffu, sum1, 2);
        l0 = l0 * a0 + sum0;
        l1 = l1 * a1 + sum1;

#pragma unroll
        for (int nt = 0; nt < 8; nt++) {
            o[nt][0] *= a0; o[nt][1] *= a0;
            o[nt][2] *= a1; o[nt][3] *= a1;
        }

#pragma unroll
        for (int nt = 0; nt < 8; nt++) {
            const int c = nt * 8 + 2 * qd;
            *(float2*)&Ps[r0 * QS + c]       = make_float2(f2tff(s[nt][0]), f2tff(s[nt][1]));
            *(float2*)&Ps[(r0 + 8) * QS + c] = make_float2(f2tff(s[nt][2]), f2tff(s[nt][3]));
        }
        __syncwarp();

#pragma unroll
        for (int ks = 0; ks < 8; ks++) {
            const int k0 = ks * 8;
            uint32_t a[4];
            a[0] = __float_as_uint(Ps[r0 * QS + k0 + qd]);
            a[1] = __float_as_uint(Ps[(r0 + 8) * QS + k0 + qd]);
            a[2] = __float_as_uint(Ps[r0 * QS + k0 + qd + 4]);
            a[3] = __float_as_uint(Ps[(r0 + 8) * QS + k0 + qd + 4]);
#pragma unroll
            for (int nt = 0; nt < 8; nt++) {
                float2 b2 = *(const float2*)&Vf[(ks * KFSTR + nt * NTSTR + lane) * 2];
                mma8(o[nt], a, (const uint32_t*)&b2);
            }
        }
    }

    if (nc == 1) {
        const float inv0 = 1.0f / l0;
        const float inv1 = 1.0f / l1;
        float* op = out + ((size_t)b * TT + qt * 128) * HDD;
#pragma unroll
        for (int nt = 0; nt < 8; nt++) {
            const int c = nt * 8 + 2 * qd;
            *(float2*)&op[(size_t)r0 * HDD + c]       = make_float2(o[nt][0] * inv0, o[nt][1] * inv0);
            *(float2*)&op[(size_t)(r0 + 8) * HDD + c] = make_float2(o[nt][2] * inv1, o[nt][3] * inv1);
        }
    } else {
        const int pidx = (b * 16 + qt) * 4 + ck;
        float* po = g_po + (size_t)pidx * 128 * HDD;
#pragma unroll
        for (int nt = 0; nt < 8; nt++) {
            const int c = nt * 8 + 2 * qd;
            *(float2*)&po[(size_t)r0 * HDD + c]       = make_float2(o[nt][0], o[nt][1]);
            *(float2*)&po[(size_t)(r0 + 8) * HDD + c] = make_float2(o[nt][2], o[nt][3]);
        }
        if (qd == 0) {
            g_pm[pidx * 128 + r0]     = m0;
            g_pm[pidx * 128 + r0 + 8] = m1;
            g_pl[pidx * 128 + r0]     = l0;
            g_pl[pidx * 128 + r0 + 8] = l1;
        }
    }
}

// ---------------------------------------------------------------------------
// Stage 3: combine split-kv partials (base-2 domain). grid (12, 8).
// ---------------------------------------------------------------------------
__global__ __launch_bounds__(256) void combine_kernel(float* __restrict__ out)
{
    const int qt  = blockIdx.x + 4;
    const int b   = blockIdx.y;
    const int nc  = (qt + 4) >> 2;
    const int tid = threadIdx.x;
    const int r    = tid >> 1;
    const int half = (tid & 1) * 32;
    const int base = (b * 16 + qt) * 4;

    float m[4], l[4], w[4];
    float mstar = -1e30f;
#pragma unroll 4
    for (int c = 0; c < nc; c++) {
        m[c] = g_pm[(base + c) * 128 + r];
        l[c] = g_pl[(base + c) * 128 + r];
        mstar = fmaxf(mstar, m[c]);
    }
    float lstar = 0.0f;
#pragma unroll 4
    for (int c = 0; c < nc; c++) {
        float e;
        asm("ex2.approx.f32 %0, %1;" : "=f"(e) : "f"(m[c] - mstar));
        w[c] = e;
        lstar += e * l[c];
    }
    const float inv = 1.0f / lstar;
#pragma unroll 4
    for (int c = 0; c < nc; c++) w[c] *= inv;

    float* op = out + ((size_t)b * TT + qt * 128 + r) * HDD + half;
#pragma unroll
    for (int g = 0; g < 8; g++) {
        float4 acc = make_float4(0.f, 0.f, 0.f, 0.f);
#pragma unroll 4
        for (int c = 0; c < nc; c++) {
            const float4 v = *(const float4*)&g_po[(size_t)(base + c) * 128 * HDD + r * HDD + half + g * 4];
            acc.x += w[c] * v.x; acc.y += w[c] * v.y;
            acc.z += w[c] * v.z; acc.w += w[c] * v.w;
        }
        *(float4*)&op[g * 4] = acc;
    }
}

// ---------------------------------------------------------------------------
// launch
// ---------------------------------------------------------------------------
extern "C" void kernel_launch(void* const* d_in, const int* in_sizes, int n_in,
                              void* d_out, int out_size)
{
    const float* x  = (const float*)d_in[0];
    const float* Wq = (const float*)d_in[1];
    const float* Wk = (const float*)d_in[2];
    const float* Wv = (const float*)d_in[3];
    float* out = (float*)d_out;

    wf_kernel<<<768, 256>>>(Wq, Wk, Wv);

    cudaFuncSetAttribute(qkv_kernel, cudaFuncAttributeMaxDynamicSharedMemorySize,
                         QKV_SMEM_BYTES);
    qkv_kernel<<<MM / 128, 256, QKV_SMEM_BYTES>>>(x);

    cudaFuncSetAttribute(attn_kernel, cudaFuncAttributeMaxDynamicSharedMemorySize,
                         ATTN_SMEM_BYTES);
    attn_kernel<<<320, 256, ATTN_SMEM_BYTES>>>(out);

    combine_kernel<<<dim3(12, 8), 256>>>(out);
}

// round 17
// speedup vs baseline: 1.7992x; 1.0379x over previous
#include <cuda_runtime.h>
#include <cstdint>

// Problem constants
#define BB 8
#define TT 2048
#define EE 1024
#define HDD 64
#define MM (BB * TT)          // 16384 rows
// SCALE * log2(e): folded into Q so softmax runs in base-2 domain
#define SCALE_LOG2E 0.1803368801111601f

// Scratch for q,k,v projections (stored pre-rounded to tf32), 4 MB each
__device__ float g_q[MM * HDD];
__device__ float g_k[MM * HDD];
__device__ float g_v[MM * HDD];
// W pre-packed into per-chunk B-fragment smem image (tf32-rounded):
// [chunk 32][ks 4][nt 24][33 float2]  -> 6336 floats per chunk
#define WF_CHUNK 6336
__device__ float g_wf[32 * WF_CHUNK];
// Split-kv partials: [b][qt][chunk] x (128 rows x 64 cols) + per-row m,l
__device__ float g_po[BB * 16 * 4 * 128 * HDD];
__device__ float g_pm[BB * 16 * 4 * 128];
__device__ float g_pl[BB * 16 * 4 * 128];

// Longest-chunk-first dispatch table for attn (entry = qt*4 + ck).
__constant__ uint8_t c_sched[40] = {
    12, 16, 20, 24, 28, 29, 32, 33, 36, 37, 40, 41, 44, 45, 46,
    48, 49, 50, 52, 53, 54, 56, 57, 58, 60, 61, 62, 63,
    8, 25, 42, 59,
    4, 21, 38, 55,
    0, 17, 34, 51
};

// ---------------------------------------------------------------------------
// helpers
// ---------------------------------------------------------------------------
__device__ __forceinline__ float f2tff(float x) {
    uint32_t u;
    asm("cvt.rna.tf32.f32 %0, %1;" : "=r"(u) : "f"(x));
    return __uint_as_float(u);
}

__device__ __forceinline__ float ex2(float x) {
    float r;
    asm("ex2.approx.f32 %0, %1;" : "=f"(r) : "f"(x));
    return r;
}

__device__ __forceinline__ void mma8(float* c, const uint32_t* a, const uint32_t* b) {
    asm volatile(
        "mma.sync.aligned.m16n8k8.row.col.f32.tf32.tf32.f32 "
        "{%0,%1,%2,%3}, {%4,%5,%6,%7}, {%8,%9}, {%0,%1,%2,%3};"
        : "+f"(c[0]), "+f"(c[1]), "+f"(c[2]), "+f"(c[3])
        : "r"(a[0]), "r"(a[1]), "r"(a[2]), "r"(a[3]), "r"(b[0]), "r"(b[1]));
}

// ---------------------------------------------------------------------------
// Stage 0: pre-pack W (tf32) into per-chunk B-fragment layout.
// 196608 elements, grid 768 x 256.
// ---------------------------------------------------------------------------
__global__ void wf_kernel(const float* __restrict__ Wq,
                          const float* __restrict__ Wk,
                          const float* __restrict__ Wv)
{
    const int idx = blockIdx.x * 256 + threadIdx.x;      // 0..196607
    const int h   = idx >> 16;                            // head 0..2
    const int rem = idx & 65535;                          // kk*64 + c
    const int kk  = rem >> 6;                             // k row 0..1023
    const int c   = rem & 63;                             // col 0..63
    const float* W = (h == 0) ? Wq : (h == 1) ? Wk : Wv;
    const float v = f2tff(W[rem]);
    const int kbi  = kk >> 5;
    const int r    = kk & 31;
    const int ks   = r >> 3;
    const int qd   = r & 3;
    const int half = (r >> 2) & 1;
    const int nt   = h * 8 + (c >> 3);
    const int gp   = c & 7;
    g_wf[kbi * WF_CHUNK + (ks * 792 + nt * 33 + gp * 4 + qd) * 2 + half] = v;
}

// ---------------------------------------------------------------------------
// Stage 1: fused QKV projection, fragment-ordered smem operands.
// CTA tile 128 rows x 192 cols. grid 128, block 256.
// ---------------------------------------------------------------------------
#define XF_BLK 132
#define XF_BUF (8 * 4 * XF_BLK)         // 4224 floats
#define WF_BUF WF_CHUNK                 // 6336 floats
#define QKV_SMEM_BYTES ((2 * XF_BUF + 2 * WF_BUF) * 4)   // 84480

__global__ __launch_bounds__(256) void qkv_kernel(const float* __restrict__ x)
{
    extern __shared__ float sm[];
    float* Xs = sm;                      // [2][4224]
    float* Ws = sm + 2 * XF_BUF;         // [2][6336]

    const int tid  = threadIdx.x;
    const int warp = tid >> 5;
    const int lane = tid & 31;
    const int qd   = lane & 3;
    const int gp   = lane >> 2;
    const int wr   = warp & 1;
    const int wc   = warp >> 1;

    const int row0 = blockIdx.x * 128;

    float acc[4][6][4];
#pragma unroll
    for (int mt = 0; mt < 4; mt++)
#pragma unroll
        for (int nt = 0; nt < 6; nt++)
#pragma unroll
            for (int i = 0; i < 4; i++) acc[mt][nt][i] = 0.0f;

    float4 xr[4];
    float4 wf4[7];
    const float4* gwf4 = (const float4*)g_wf;

#pragma unroll
    for (int p = 0; p < 4; p++) {
        const int idx = tid + p * 256;
        xr[p] = *(const float4*)&x[(size_t)(row0 + (idx >> 3)) * EE + (idx & 7) * 4];
    }
#pragma unroll
    for (int p = 0; p < 7; p++) {
        const int idx = tid + p * 256;
        if (idx < WF_CHUNK / 4) wf4[p] = gwf4[idx];
    }

    for (int kbi = 0; kbi < 32; kbi++) {
        float* Xb = Xs + (kbi & 1) * XF_BUF;
        float* Wb = Ws + (kbi & 1) * WF_BUF;

#pragma unroll
        for (int p = 0; p < 4; p++) {
            const int idx = tid + p * 256;
            const int r  = idx >> 3;
            const int c4 = (idx & 7) * 4;
            const int mtile   = r >> 4;
            const int rr      = r & 15;
            const int gpq     = rr & 7;
            const int regbase = rr >> 3;
            const int ks      = c4 >> 3;
            const int khalf   = (c4 >> 2) & 1;
            float* d = &Xb[(mtile * 4 + ks) * XF_BLK + gpq * 16 + regbase + 2 * khalf];
            d[0]  = f2tff(xr[p].x);
            d[4]  = f2tff(xr[p].y);
            d[8]  = f2tff(xr[p].z);
            d[12] = f2tff(xr[p].w);
        }
        {
            float4* wdst = (float4*)Wb;
#pragma unroll
            for (int p = 0; p < 7; p++) {
                const int idx = tid + p * 256;
                if (idx < WF_CHUNK / 4) wdst[idx] = wf4[p];
            }
        }

        if (kbi < 31) {
            const int kb = (kbi + 1) * 32;
#pragma unroll
            for (int p = 0; p < 4; p++) {
                const int idx = tid + p * 256;
                xr[p] = *(const float4*)&x[(size_t)(row0 + (idx >> 3)) * EE + kb + (idx & 7) * 4];
            }
            const float4* src = gwf4 + (size_t)(kbi + 1) * (WF_CHUNK / 4);
#pragma unroll
            for (int p = 0; p < 7; p++) {
                const int idx = tid + p * 256;
                if (idx < WF_CHUNK / 4) wf4[p] = src[idx];
            }
        }
        __syncthreads();

#pragma unroll
        for (int ks = 0; ks < 4; ks++) {
            uint4 aq[4];
#pragma unroll
            for (int mt = 0; mt < 4; mt++)
                aq[mt] = *(const uint4*)&Xb[((wr * 4 + mt) * 4 + ks) * XF_BLK + lane * 4];
#pragma unroll
            for (int j = 0; j < 6; j++) {
                float2 b2 = *(const float2*)&Wb[(ks * 792 + (wc * 6 + j) * 33 + lane) * 2];
#pragma unroll
                for (int mt = 0; mt < 4; mt++)
                    mma8(acc[mt][j], (const uint32_t*)&aq[mt], (const uint32_t*)&b2);
            }
        }
    }

#pragma unroll
    for (int mt = 0; mt < 4; mt++) {
#pragma unroll
        for (int nt = 0; nt < 6; nt++) {
            const int r = row0 + wr * 64 + mt * 16 + gp;
            const int col192 = wc * 48 + nt * 8 + 2 * qd;
            float* outp = (col192 < 64) ? g_q : (col192 < 128) ? g_k : g_v;
            const int c = col192 & 63;
            *(float2*)&outp[(size_t)r * HDD + c] =
                make_float2(f2tff(acc[mt][nt][0]), f2tff(acc[mt][nt][1]));
            *(float2*)&outp[(size_t)(r + 8) * HDD + c] =
                make_float2(f2tff(acc[mt][nt][2]), f2tff(acc[mt][nt][3]));
        }
    }
}

// ---------------------------------------------------------------------------
// Stage 2: split-kv causal flash attention (unchanged from R13/R15 best).
// ---------------------------------------------------------------------------
#define NTSTR 33
#define KFSTR 266
#define QF_FLOATS 8192
#define KF_FLOATS (8 * KFSTR * 2)
#define QS 68
#define PS_OFF (QF_FLOATS + 2 * KF_FLOATS)
#define ATTN_SMEM_BYTES ((PS_OFF + 128 * QS) * 4)             // 101632

__global__ __launch_bounds__(256, 2) void attn_kernel(float* __restrict__ out)
{
    extern __shared__ float sm[];
    float* Qf = sm;
    float* Kf = sm + QF_FLOATS;
    float* Vf = sm + QF_FLOATS + KF_FLOATS;
    float* Ps = sm + PS_OFF;

    const int tid  = threadIdx.x;
    const int warp = tid >> 5;
    const int lane = tid & 31;
    const int qd   = lane & 3;
    const int gp   = lane >> 2;

    const int b    = blockIdx.x & 7;
    const int code = c_sched[blockIdx.x >> 3];
    const int qt   = code >> 2;
    const int ck   = code & 3;

    const int nc = (qt + 4) >> 2;
    const int j0 = ck * 8;
    const int j1 = min(ck * 8 + 8, 2 * (qt + 1));

    const int ldr  = tid >> 4;
    const int ldc4 = (tid & 15) * 4;

    {
        const float* qptr = g_q + ((size_t)b * TT + qt * 128) * HDD;
        const int ksq   = ldc4 >> 3;
        const int khalf = (ldc4 >> 2) & 1;
#pragma unroll
        for (int p = 0; p < 8; p++) {
            const int row = ldr + p * 16;
            float4 v = *(const float4*)&qptr[(size_t)row * HDD + ldc4];
            const int w   = row >> 4;
            const int rr  = row & 15;
            const int gpq = rr & 7;
            const int regidx = (rr >> 3) + 2 * khalf;
            float* d = &Qf[((w * 8 + ksq) * 32 + gpq * 4) * 4 + regidx];
            d[0]  = f2tff(v.x * SCALE_LOG2E);
            d[4]  = f2tff(v.y * SCALE_LOG2E);
            d[8]  = f2tff(v.z * SCALE_LOG2E);
            d[12] = f2tff(v.w * SCALE_LOG2E);
        }
    }

    const int r0  = warp * 16 + gp;
    const int rg0 = qt * 128 + r0;

    float m0 = -1e30f, m1 = -1e30f, l0 = 0.0f, l1 = 0.0f;
    float o[8][4];
#pragma unroll
    for (int nt = 0; nt < 8; nt++)
#pragma unroll
        for (int i = 0; i < 4; i++) o[nt][i] = 0.0f;

    float4 kr[4], vr[4];
    {
        const float* kp = g_k + ((size_t)b * TT + j0 * 64) * HDD;
        const float* vp = g_v + ((size_t)b * TT + j0 * 64) * HDD;
#pragma unroll
        for (int p = 0; p < 4; p++) {
            kr[p] = *(const float4*)&kp[(size_t)(ldr + p * 16) * HDD + ldc4];
            vr[p] = *(const float4*)&vp[(size_t)(ldr + p * 16) * HDD + ldc4];
        }
    }

    const int kskA  = ldc4 >> 3;
    const int halfA = (ldc4 >> 2) & 1;
    const int ntV   = ldc4 >> 3;
    const int gpbV  = ldc4 & 7;

    for (int j64 = j0; j64 < j1; j64++) {
        __syncthreads();
#pragma unroll
        for (int p = 0; p < 4; p++) {
            const int n  = ldr + p * 16;
            {
                float* d = &Kf[(kskA * KFSTR + (n >> 3) * NTSTR + (n & 7) * 4) * 2 + halfA];
                d[0] = kr[p].x; d[2] = kr[p].y; d[4] = kr[p].z; d[6] = kr[p].w;
            }
            {
                float* d = &Vf[((n >> 3) * KFSTR + ntV * NTSTR + gpbV * 4 + (n & 3)) * 2 + ((n >> 2) & 1)];
                d[0] = vr[p].x; d[8] = vr[p].y; d[16] = vr[p].z; d[24] = vr[p].w;
            }
        }
        if (j64 + 1 < j1) {
            const float* kp = g_k + ((size_t)b * TT + (j64 + 1) * 64) * HDD;
            const float* vp = g_v + ((size_t)b * TT + (j64 + 1) * 64) * HDD;
#pragma unroll
            for (int p = 0; p < 4; p++) {
                kr[p] = *(const float4*)&kp[(size_t)(ldr + p * 16) * HDD + ldc4];
                vr[p] = *(const float4*)&vp[(size_t)(ldr + p * 16) * HDD + ldc4];
            }
        }
        __syncthreads();

        float s[8][4];
#pragma unroll
        for (int nt = 0; nt < 8; nt++)
#pragma unroll
            for (int i = 0; i < 4; i++) s[nt][i] = 0.0f;

#pragma unroll
        for (int ks = 0; ks < 8; ks++) {
            uint4 aq = *(const uint4*)&Qf[((warp * 8 + ks) * 32 + lane) * 4];
#pragma unroll
            for (int nt = 0; nt < 8; nt++) {
                float2 b2 = *(const float2*)&Kf[(ks * KFSTR + nt * NTSTR + lane) * 2];
                mma8(s[nt], (const uint32_t*)&aq, (const uint32_t*)&b2);
            }
        }

        if (j64 >= 2 * qt) {
#pragma unroll
            for (int nt = 0; nt < 8; nt++) {
                const int c = j64 * 64 + nt * 8 + 2 * qd;
                if (c     > rg0)     s[nt][0] = -1e30f;
                if (c + 1 > rg0)     s[nt][1] = -1e30f;
                if (c     > rg0 + 8) s[nt][2] = -1e30f;
                if (c + 1 > rg0 + 8) s[nt][3] = -1e30f;
            }
        }

        float mx0 = -1e30f, mx1 = -1e30f;
#pragma unroll
        for (int nt = 0; nt < 8; nt++) {
            mx0 = fmaxf(mx0, fmaxf(s[nt][0], s[nt][1]));
            mx1 = fmaxf(mx1, fmaxf(s[nt][2], s[nt][3]));
        }
        mx0 = fmaxf(mx0, __shfl_xor_sync(0xffffffffu, mx0, 1));
        mx0 = fmaxf(mx0, __shfl_xor_sync(0xffffffffu, mx0, 2));
        mx1 = fmaxf(mx1, __shfl_xor_sync(0xffffffffu, mx1, 1));
        mx1 = fmaxf(mx1, __shfl_xor_sync(0xffffffffu, mx1, 2));

        const float nm0 = fmaxf(m0, mx0);
        const float nm1 = fmaxf(m1, mx1);
        const float a0 = ex2(m0 - nm0);
        const float a1 = ex2(m1 - nm1);
        m0 = nm0; m1 = nm1;

        float sum0 = 0.0f, sum1 = 0.0f;
#pragma unroll
        for (int nt = 0; nt < 8; nt++) {
            s[nt][0] = ex2(s[nt][0] - nm0);
            s[nt][1] = ex2(s[nt][1] - nm0);
            s[nt][2] = ex2(s[nt][2] - nm1);
            s[nt][3] = ex2(s[nt][3] - nm1);
            sum0 += s[nt][0] + s[nt][1];
            sum1 += s[nt][2] + s[nt][3];
        }
        sum0 += __shfl_xor_sync(0xffffffffu, sum0, 1);
        sum0 += __shfl_xor_sync(0xffffffffu, sum0, 2);
        sum1 += __shfl_xor_sync(0xffffffffu, sum1, 1);
        sum1 += __shfl_xor_sync(0xffffffffu, sum1, 2);
        l0 = l0 * a0 + sum0;
        l1 = l1 * a1 + sum1;

#pragma unroll
        for (int nt = 0; nt < 8; nt++) {
            o[nt][0] *= a0; o[nt][1] *= a0;
            o[nt][2] *= a1; o[nt][3] *= a1;
        }

#pragma unroll
        for (int nt = 0; nt < 8; nt++) {
            const int c = nt * 8 + 2 * qd;
            *(float2*)&Ps[r0 * QS + c]       = make_float2(f2tff(s[nt][0]), f2tff(s[nt][1]));
            *(float2*)&Ps[(r0 + 8) * QS + c] = make_float2(f2tff(s[nt][2]), f2tff(s[nt][3]));
        }
        __syncwarp();

#pragma unroll
        for (int ks = 0; ks < 8; ks++) {
            const int k0 = ks * 8;
            uint32_t a[4];
            a[0] = __float_as_uint(Ps[r0 * QS + k0 + qd]);
            a[1] = __float_as_uint(Ps[(r0 + 8) * QS + k0 + qd]);
            a[2] = __float_as_uint(Ps[r0 * QS + k0 + qd + 4]);
            a[3] = __float_as_uint(Ps[(r0 + 8) * QS + k0 + qd + 4]);
#pragma unroll
            for (int nt = 0; nt < 8; nt++) {
                float2 b2 = *(const float2*)&Vf[(ks * KFSTR + nt * NTSTR + lane) * 2];
                mma8(o[nt], a, (const uint32_t*)&b2);
            }
        }
    }

    if (nc == 1) {
        const float inv0 = 1.0f / l0;
        const float inv1 = 1.0f / l1;
        float* op = out + ((size_t)b * TT + qt * 128) * HDD;
#pragma unroll
        for (int nt = 0; nt < 8; nt++) {
            const int c = nt * 8 + 2 * qd;
            *(float2*)&op[(size_t)r0 * HDD + c]       = make_float2(o[nt][0] * inv0, o[nt][1] * inv0);
            *(float2*)&op[(size_t)(r0 + 8) * HDD + c] = make_float2(o[nt][2] * inv1, o[nt][3] * inv1);
        }
    } else {
        const int pidx = (b * 16 + qt) * 4 + ck;
        float* po = g_po + (size_t)pidx * 128 * HDD;
#pragma unroll
        for (int nt = 0; nt < 8; nt++) {
            const int c = nt * 8 + 2 * qd;
            *(float2*)&po[(size_t)r0 * HDD + c]       = make_float2(o[nt][0], o[nt][1]);
            *(float2*)&po[(size_t)(r0 + 8) * HDD + c] = make_float2(o[nt][2], o[nt][3]);
        }
        if (qd == 0) {
            g_pm[pidx * 128 + r0]     = m0;
            g_pm[pidx * 128 + r0 + 8] = m1;
            g_pl[pidx * 128 + r0]     = l0;
            g_pl[pidx * 128 + r0 + 8] = l1;
        }
    }
}

// ---------------------------------------------------------------------------
// Stage 3: combine split-kv partials — one float4 output per thread.
// 12 qt x 8 b x 128 rows x 16 groups = 196608 threads, grid 768 x 256.
// ---------------------------------------------------------------------------
__global__ __launch_bounds__(256) void combine_kernel(float* __restrict__ out)
{
    const int idx = blockIdx.x * 256 + threadIdx.x;   // 0..196607
    const int g   = idx & 15;                          // float4 group in row
    const int r   = (idx >> 4) & 127;                  // row in tile
    const int b   = (idx >> 11) & 7;                   // batch
    const int qt  = (idx >> 14) + 4;                   // 4..15
    const int nc  = (qt + 4) >> 2;                     // 2..4
    const int base = (b * 16 + qt) * 4;

    float m[4], l[4];
    float mstar = -1e30f;
#pragma unroll 4
    for (int c = 0; c < nc; c++) {
        m[c] = g_pm[(base + c) * 128 + r];
        l[c] = g_pl[(base + c) * 128 + r];
        mstar = fmaxf(mstar, m[c]);
    }
    float w[4];
    float lstar = 0.0f;
#pragma unroll 4
    for (int c = 0; c < nc; c++) {
        w[c] = ex2(m[c] - mstar);
        lstar += w[c] * l[c];
    }
    const float inv = 1.0f / lstar;

    float4 acc = make_float4(0.f, 0.f, 0.f, 0.f);
#pragma unroll 4
    for (int c = 0; c < nc; c++) {
        const float4 v = *(const float4*)&g_po[(size_t)(base + c) * 128 * HDD + r * HDD + g * 4];
        const float wc_ = w[c] * inv;
        acc.x += wc_ * v.x; acc.y += wc_ * v.y;
        acc.z += wc_ * v.z; acc.w += wc_ * v.w;
    }
    *(float4*)&out[((size_t)b * TT + qt * 128 + r) * HDD + g * 4] = acc;
}

// ---------------------------------------------------------------------------
// launch
// ---------------------------------------------------------------------------
extern "C" void kernel_launch(void* const* d_in, const int* in_sizes, int n_in,
                              void* d_out, int out_size)
{
    const float* x  = (const float*)d_in[0];
    const float* Wq = (const float*)d_in[1];
    const float* Wk = (const float*)d_in[2];
    const float* Wv = (const float*)d_in[3];
    float* out = (float*)d_out;

    wf_kernel<<<768, 256>>>(Wq, Wk, Wv);

    cudaFuncSetAttribute(qkv_kernel, cudaFuncAttributeMaxDynamicSharedMemorySize,
                         QKV_SMEM_BYTES);
    qkv_kernel<<<MM / 128, 256, QKV_SMEM_BYTES>>>(x);

    cudaFuncSetAttribute(attn_kernel, cudaFuncAttributeMaxDynamicSharedMemorySize,
                         ATTN_SMEM_BYTES);
    attn_kernel<<<320, 256, ATTN_SMEM_BYTES>>>(out);

    combine_kernel<<<768, 256>>>(out);
}